// round 6
// baseline (speedup 1.0000x reference)
#include <cuda_runtime.h>
#include <cstdint>
#include <math.h>

#define D_MODEL 2048
#define SEQ     2048
#define N_HEADS 16
#define HEAD_DIM 128

// Scratch (no cudaMalloc allowed)
__device__ float g_Q[SEQ * D_MODEL];
__device__ float g_K[SEQ * D_MODEL];
__device__ float g_V[SEQ * D_MODEL];
__device__ float g_A[SEQ * D_MODEL];
__device__ float g_X[SEQ * D_MODEL];
__device__ float g_WT4[4 * D_MODEL * D_MODEL];

// ---------------------------------------------------------------------------
// helpers
// ---------------------------------------------------------------------------
static __device__ __forceinline__ uint32_t smem_u32(const void* p) {
    return (uint32_t)__cvta_generic_to_shared(p);
}

#define LDSM_X4(r0, r1, r2, r3, addr) \
    asm volatile("ldmatrix.sync.aligned.m8n8.x4.shared.b16 {%0,%1,%2,%3}, [%4];" \
                 : "=r"(r0), "=r"(r1), "=r"(r2), "=r"(r3) : "r"(addr))

static __device__ __forceinline__ void mma_tf32(
    float* c, const uint32_t* a, uint32_t b0, uint32_t b1)
{
    asm volatile(
        "mma.sync.aligned.m16n8k8.row.col.f32.tf32.tf32.f32 "
        "{%0,%1,%2,%3}, {%4,%5,%6,%7}, {%8,%9}, {%0,%1,%2,%3};"
        : "+f"(c[0]), "+f"(c[1]), "+f"(c[2]), "+f"(c[3])
        : "r"(a[0]), "r"(a[1]), "r"(a[2]), "r"(a[3]), "r"(b0), "r"(b1));
}

static __device__ __forceinline__ float round_tf32(float x) {
    uint32_t r;
    asm("cvt.rna.tf32.f32 %0, %1;" : "=r"(r) : "f"(x));
    return __uint_as_float(r);
}

static __device__ __forceinline__ void sts_tf32x4(uint32_t addr, float4 v) {
    uint32_t a, b, c, d;
    asm("cvt.rna.tf32.f32 %0, %1;" : "=r"(a) : "f"(v.x));
    asm("cvt.rna.tf32.f32 %0, %1;" : "=r"(b) : "f"(v.y));
    asm("cvt.rna.tf32.f32 %0, %1;" : "=r"(c) : "f"(v.z));
    asm("cvt.rna.tf32.f32 %0, %1;" : "=r"(d) : "f"(v.w));
    asm volatile("st.shared.v4.b32 [%0], {%1, %2, %3, %4};"
                 :: "r"(addr), "r"(a), "r"(b), "r"(c), "r"(d) : "memory");
}

static __device__ __forceinline__ void sts_tf32(uint32_t addr, float v) {
    uint32_t a;
    asm("cvt.rna.tf32.f32 %0, %1;" : "=r"(a) : "f"(v));
    asm volatile("st.shared.b32 [%0], %1;" :: "r"(addr), "r"(a) : "memory");
}

static __device__ __forceinline__ void sts_tf32x2(uint32_t addr, float x, float y) {
    uint32_t a, b;
    asm("cvt.rna.tf32.f32 %0, %1;" : "=r"(a) : "f"(x));
    asm("cvt.rna.tf32.f32 %0, %1;" : "=r"(b) : "f"(y));
    asm volatile("st.shared.v2.b32 [%0], {%1, %2};"
                 :: "r"(addr), "r"(a), "r"(b) : "memory");
}

static __device__ __forceinline__ void cp_async16(uint32_t dst, const void* src) {
    asm volatile("cp.async.cg.shared.global [%0], [%1], 16;"
                 :: "r"(dst), "l"(src) : "memory");
}
#define CP_COMMIT() asm volatile("cp.async.commit_group;" ::: "memory")

// ---------------------------------------------------------------------------
// prep: z=0 round-copy x ; z=1..4 transpose+round wq/wk/wv/wo into WT slabs
// ---------------------------------------------------------------------------
__global__ __launch_bounds__(256) void prep_kernel(
    const float* __restrict__ x,
    const float* __restrict__ wq, const float* __restrict__ wk,
    const float* __restrict__ wv, const float* __restrict__ wo,
    float* __restrict__ X, float* __restrict__ WT)
{
    const size_t WSZ = (size_t)D_MODEL * D_MODEL;
    int z = blockIdx.z;
    if (z == 0) {
        int c = blockIdx.x * 32 + threadIdx.x;
#pragma unroll
        for (int i = 0; i < 4; i++) {
            int r = blockIdx.y * 32 + threadIdx.y + i * 8;
            X[(size_t)r * D_MODEL + c] = round_tf32(x[(size_t)r * D_MODEL + c]);
        }
        return;
    }
    const float* in = (z == 1) ? wq : (z == 2) ? wk : (z == 3) ? wv : wo;
    float* out = WT + (size_t)(z - 1) * WSZ;

    __shared__ float tile[32][33];
    int xx = blockIdx.x * 32 + threadIdx.x;
    int yy = blockIdx.y * 32 + threadIdx.y;
#pragma unroll
    for (int i = 0; i < 32; i += 8)
        tile[threadIdx.y + i][threadIdx.x] = in[(size_t)(yy + i) * D_MODEL + xx];
    __syncthreads();
    xx = blockIdx.y * 32 + threadIdx.x;
    yy = blockIdx.x * 32 + threadIdx.y;
#pragma unroll
    for (int i = 0; i < 32; i += 8)
        out[(size_t)(yy + i) * D_MODEL + xx] = round_tf32(tile[threadIdx.x][threadIdx.y + i]);
}

// ---------------------------------------------------------------------------
// tf32 mma.sync GEMM v2: CTA tile 128x256, warp tile 64x64, BK=32,
// 3-stage cp.async pipeline. Inputs must be pre-rounded tf32.
// BT is [n_total, 2048] (= B^T); bx selects a 256-row slab of BT.
// mat = bx / tiles_per_mat selects C0/C1/C2; col0 = (bx % tiles_per_mat)*256.
// If mat < rope_mats, RoPE is applied in the epilogue (cols are rotary pairs).
// ---------------------------------------------------------------------------
#define GSTAGES 3
#define GSTAGE_BYTES 49152            // A 16KB + B 32KB
#define GEMM_SMEM_BYTES (GSTAGES * GSTAGE_BYTES)

__global__ __launch_bounds__(256, 1) void gemm_tc_kernel(
    const float* __restrict__ A, const float* __restrict__ BT,
    float* __restrict__ C0, float* __restrict__ C1, float* __restrict__ C2,
    const float* __restrict__ fc, const float* __restrict__ fs,
    int tiles_per_mat, int rope_mats)
{
    extern __shared__ char smc[];
    uint32_t sb = smem_u32(smc);

    int t    = threadIdx.x;
    int lane = t & 31;
    int wid  = t >> 5;
    int row0 = blockIdx.y << 7;
    int bx   = blockIdx.x;
    int mat  = bx / tiles_per_mat;
    int col0 = (bx % tiles_per_mat) << 8;
    float* C = (mat == 0) ? C0 : (mat == 1 ? C1 : C2);
    const float* Arow = A + (size_t)row0 * D_MODEL;
    const float* Brow = BT + ((size_t)bx << 8) * D_MODEL;
    bool dorope = (mat < rope_mats);

    int wm = (wid >> 2) << 6;    // 0 / 64
    int wn = (wid & 3) << 6;     // 0 / 64 / 128 / 192

    float acc[4][8][4];
#pragma unroll
    for (int i = 0; i < 4; i++)
#pragma unroll
        for (int j = 0; j < 8; j++)
#pragma unroll
            for (int q = 0; q < 4; q++) acc[i][j][q] = 0.0f;

    uint32_t arow  = (uint32_t)(wm + (lane & 7) + ((lane >> 3) & 1) * 8);
    uint32_t acsel = (uint32_t)((lane >> 4) & 1);
    uint32_t brow  = (uint32_t)(wn + (lane & 7) + ((lane >> 4) & 1) * 8);
    uint32_t bcsel = (uint32_t)((lane >> 3) & 1);
    uint32_t asw7  = arow & 7;
    uint32_t bsw7  = brow & 7;

    // copy geometry: cr=row base 0..31, cc=16B chunk 0..7
    const int cr = t >> 3;
    const int cc = t & 7;
    const uint32_t csw = (uint32_t)((cr << 7) + ((cc ^ (cr & 7)) << 4));

    const int NCHUNK = D_MODEL / 32;   // 64

    // prologue: stages 0,1
#pragma unroll
    for (int pc = 0; pc < 2; pc++) {
        uint32_t abuf = sb + (uint32_t)pc * GSTAGE_BYTES;
        uint32_t bbuf = abuf + 16384u;
        const float* Ag = Arow + (pc << 5);
        const float* Bg = Brow + (pc << 5);
#pragma unroll
        for (int i = 0; i < 4; i++)
            cp_async16(abuf + csw + (uint32_t)(i << 12),
                       Ag + (size_t)(cr + (i << 5)) * D_MODEL + (cc << 2));
#pragma unroll
        for (int i = 0; i < 8; i++)
            cp_async16(bbuf + csw + (uint32_t)(i << 12),
                       Bg + (size_t)(cr + (i << 5)) * D_MODEL + (cc << 2));
        CP_COMMIT();
    }

    int stage = 0;
#pragma unroll 1
    for (int c = 0; c < NCHUNK; c++) {
        if (c + 1 < NCHUNK) asm volatile("cp.async.wait_group 1;" ::: "memory");
        else                asm volatile("cp.async.wait_group 0;" ::: "memory");
        __syncthreads();

        uint32_t ab = sb + (uint32_t)stage * GSTAGE_BYTES;
        uint32_t bb = ab + 16384u;

#pragma unroll
        for (int s = 0; s < 4; s++) {
            uint32_t af[4][4], bf[4][4];
#pragma unroll
            for (int mt = 0; mt < 4; mt++) {
                uint32_t addr = ab + ((arow + mt * 16) << 7)
                                   + (((2u * s + acsel) ^ asw7) << 4);
                LDSM_X4(af[mt][0], af[mt][1], af[mt][2], af[mt][3], addr);
            }
#pragma unroll
            for (int p = 0; p < 4; p++) {
                uint32_t addr = bb + ((brow + p * 16) << 7)
                                   + (((2u * s + bcsel) ^ bsw7) << 4);
                LDSM_X4(bf[p][0], bf[p][1], bf[p][2], bf[p][3], addr);
            }
#pragma unroll
            for (int mt = 0; mt < 4; mt++)
#pragma unroll
                for (int nt = 0; nt < 8; nt++)
                    mma_tf32(acc[mt][nt], af[mt],
                             bf[nt >> 1][(nt & 1) * 2],
                             bf[nt >> 1][(nt & 1) * 2 + 1]);
        }

        __syncthreads();

        if (c + 2 < NCHUNK) {
            int nc = c + 2;
            uint32_t abuf = sb + (uint32_t)((stage + 2) % GSTAGES) * GSTAGE_BYTES;
            uint32_t bbuf = abuf + 16384u;
            const float* Ag = Arow + (nc << 5);
            const float* Bg = Brow + (nc << 5);
#pragma unroll
            for (int i = 0; i < 4; i++)
                cp_async16(abuf + csw + (uint32_t)(i << 12),
                           Ag + (size_t)(cr + (i << 5)) * D_MODEL + (cc << 2));
#pragma unroll
            for (int i = 0; i < 8; i++)
                cp_async16(bbuf + csw + (uint32_t)(i << 12),
                           Bg + (size_t)(cr + (i << 5)) * D_MODEL + (cc << 2));
        }
        CP_COMMIT();

        stage++;
        if (stage == GSTAGES) stage = 0;
    }

    // ---- epilogue (+ optional fused RoPE: cols (ce,ce+1) are rotary pairs) ----
#pragma unroll
    for (int mt = 0; mt < 4; mt++) {
        int re = row0 + wm + mt * 16 + (lane >> 2);
#pragma unroll
        for (int nt = 0; nt < 8; nt++) {
            int ce = col0 + wn + nt * 8 + ((lane & 3) << 1);
            float2 v0 = make_float2(acc[mt][nt][0], acc[mt][nt][1]);
            float2 v1 = make_float2(acc[mt][nt][2], acc[mt][nt][3]);
            if (dorope) {
                int pidx = (ce & 127) >> 1;
                float c0 = fc[(size_t)re * 64 + pidx];
                float s0 = fs[(size_t)re * 64 + pidx];
                float c1 = fc[(size_t)(re + 8) * 64 + pidx];
                float s1 = fs[(size_t)(re + 8) * 64 + pidx];
                v0 = make_float2(v0.x * c0 - v0.y * s0, v0.x * s0 + v0.y * c0);
                v1 = make_float2(v1.x * c1 - v1.y * s1, v1.x * s1 + v1.y * c1);
            }
            *(float2*)(C + (size_t)re * D_MODEL + ce)       = v0;
            *(float2*)(C + (size_t)(re + 8) * D_MODEL + ce) = v1;
        }
    }
}

// ---------------------------------------------------------------------------
// FlashAttention-2 style causal attention on tf32 mma.sync (validated R4/R5)
// ---------------------------------------------------------------------------
#define ATT_SMEM_BYTES (96 * 1024)

__global__ __launch_bounds__(256, 1) void attn_tc_kernel(
    const float* __restrict__ Q, const float* __restrict__ K,
    const float* __restrict__ V, float* __restrict__ O)
{
    extern __shared__ char smc[];
    uint32_t sb = smem_u32(smc);
    const uint32_t ks = sb;
    const uint32_t vt = sb + 32768;
    const uint32_t ps = sb + 65536;

    int t    = threadIdx.x;
    int lane = t & 31;
    int w    = t >> 5;
    int qt   = (int)gridDim.x - 1 - (int)blockIdx.x;
    int h    = blockIdx.y;
    int q0   = qt << 7;

    uint32_t arow  = (uint32_t)((lane & 7) + ((lane >> 3) & 1) * 8);
    uint32_t acsel = (uint32_t)((lane >> 4) & 1);
    uint32_t brow  = (uint32_t)((lane & 7) + ((lane >> 4) & 1) * 8);
    uint32_t bcsel = (uint32_t)((lane >> 3) & 1);
    uint32_t asw   = arow & 7;
    uint32_t bsw   = brow & 7;

    uint32_t qf[16][4];
    {
        const float4* Qg = (const float4*)(Q + (size_t)q0 * D_MODEL + h * HEAD_DIM);
#pragma unroll
        for (int i = 0; i < 16; i++) {
            int lin = t + (i << 8);
            int r   = lin >> 5;
            int c   = lin & 31;
            float4 v = Qg[(size_t)r * 512 + c];
            sts_tf32x4(sb + (r << 9) + (((uint32_t)c ^ (r & 7)) << 4), v);
        }
        __syncthreads();
        uint32_t qrow = arow + (uint32_t)(w << 4);
        uint32_t qsw  = qrow & 7;
#pragma unroll
        for (int s = 0; s < 16; s++) {
            uint32_t addr = sb + (qrow << 9) + (((2u * s + acsel) ^ qsw) << 4);
            LDSM_X4(qf[s][0], qf[s][1], qf[s][2], qf[s][3], addr);
        }
    }

    float oacc[16][4];
#pragma unroll
    for (int i = 0; i < 16; i++)
#pragma unroll
        for (int j = 0; j < 4; j++) oacc[i][j] = 0.0f;
    float mrow[2] = {-1e30f, -1e30f};
    float lrow[2] = {0.0f, 0.0f};

    const float scale = 0.08838834764831845f;
    const int   ktmax = 2 * qt + 1;
    const uint32_t pbase = ps + (uint32_t)(w << 12);

    for (int kt = 0; kt <= ktmax; kt++) {
        __syncthreads();
        {
            const float4* Kg = (const float4*)(K + ((size_t)kt << 6) * D_MODEL + h * HEAD_DIM);
            const float4* Vg = (const float4*)(V + ((size_t)kt << 6) * D_MODEL + h * HEAD_DIM);
#pragma unroll
            for (int i = 0; i < 8; i++) {
                int lin = t + (i << 8);
                int r   = lin >> 5;
                int c   = lin & 31;
                float4 kv = Kg[(size_t)r * 512 + c];
                sts_tf32x4(ks + (r << 9) + (((uint32_t)c ^ (r & 7)) << 4), kv);
                int kk = lin & 63;
                int d4 = lin >> 6;
                float4 vv = Vg[(size_t)kk * 512 + d4];
                uint32_t kchunk = (uint32_t)(kk >> 2);
                uint32_t koff   = (uint32_t)(kk & 3) << 2;
                int d = d4 << 2;
                sts_tf32(vt + ((d + 0) << 8) + ((kchunk ^ ((d + 0) & 7)) << 4) + koff, vv.x);
                sts_tf32(vt + ((d + 1) << 8) + ((kchunk ^ ((d + 1) & 7)) << 4) + koff, vv.y);
                sts_tf32(vt + ((d + 2) << 8) + ((kchunk ^ ((d + 2) & 7)) << 4) + koff, vv.z);
                sts_tf32(vt + ((d + 3) << 8) + ((kchunk ^ ((d + 3) & 7)) << 4) + koff, vv.w);
            }
        }
        __syncthreads();

        float sacc[8][4];
#pragma unroll
        for (int nt = 0; nt < 8; nt++)
#pragma unroll
            for (int e = 0; e < 4; e++) sacc[nt][e] = 0.0f;

#pragma unroll
        for (int s = 0; s < 16; s++) {
            uint32_t bf[4][4];
#pragma unroll
            for (int p = 0; p < 4; p++) {
                uint32_t addr = ks + ((brow + (uint32_t)(p << 4)) << 9)
                                   + (((2u * s + bcsel) ^ bsw) << 4);
                LDSM_X4(bf[p][0], bf[p][1], bf[p][2], bf[p][3], addr);
            }
#pragma unroll
            for (int nt = 0; nt < 8; nt++)
                mma_tf32(sacc[nt], qf[s],
                         bf[nt >> 1][(nt & 1) * 2],
                         bf[nt >> 1][(nt & 1) * 2 + 1]);
        }

        bool need_mask = (kt >= 2 * qt);
        int grow = q0 + (w << 4) + (lane >> 2);
#pragma unroll
        for (int nt = 0; nt < 8; nt++) {
#pragma unroll
            for (int e = 0; e < 4; e++) {
                float v = sacc[nt][e] * scale;
                if (need_mask) {
                    int row = grow + (e >> 1) * 8;
                    int col = (kt << 6) + (nt << 3) + ((lane & 3) << 1) + (e & 1);
                    if (col > row) v = -1e30f;
                }
                sacc[nt][e] = v;
            }
        }

        float alpha[2];
#pragma unroll
        for (int half = 0; half < 2; half++) {
            float mx = -1e30f;
#pragma unroll
            for (int nt = 0; nt < 8; nt++)
                mx = fmaxf(mx, fmaxf(sacc[nt][2 * half], sacc[nt][2 * half + 1]));
            mx = fmaxf(mx, __shfl_xor_sync(0xffffffffu, mx, 1));
            mx = fmaxf(mx, __shfl_xor_sync(0xffffffffu, mx, 2));
            float mnew = fmaxf(mrow[half], mx);
            alpha[half] = __expf(mrow[half] - mnew);
            float sum = 0.0f;
#pragma unroll
            for (int nt = 0; nt < 8; nt++) {
                float p0 = __expf(sacc[nt][2 * half]     - mnew);
                float p1 = __expf(sacc[nt][2 * half + 1] - mnew);
                sacc[nt][2 * half]     = p0;
                sacc[nt][2 * half + 1] = p1;
                sum += p0 + p1;
            }
            sum += __shfl_xor_sync(0xffffffffu, sum, 1);
            sum += __shfl_xor_sync(0xffffffffu, sum, 2);
            lrow[half] = lrow[half] * alpha[half] + sum;
            mrow[half] = mnew;
        }
#pragma unroll
        for (int nt = 0; nt < 16; nt++) {
            oacc[nt][0] *= alpha[0];  oacc[nt][1] *= alpha[0];
            oacc[nt][2] *= alpha[1];  oacc[nt][3] *= alpha[1];
        }

        {
            uint32_t prow0 = (uint32_t)(lane >> 2);
            uint32_t prow1 = prow0 + 8;
#pragma unroll
            for (int nt = 0; nt < 8; nt++) {
                uint32_t col   = (uint32_t)((nt << 3) + ((lane & 3) << 1));
                uint32_t chunk = col >> 2;
                uint32_t coff  = (col & 3) << 2;
                sts_tf32x2(pbase + (prow0 << 8) + ((chunk ^ (prow0 & 7)) << 4) + coff,
                           sacc[nt][0], sacc[nt][1]);
                sts_tf32x2(pbase + (prow1 << 8) + ((chunk ^ (prow1 & 7)) << 4) + coff,
                           sacc[nt][2], sacc[nt][3]);
            }
        }
        __syncwarp();

#pragma unroll
        for (int s = 0; s < 8; s++) {
            uint32_t pf[4];
            uint32_t addrA = pbase + (arow << 8) + (((2u * s + acsel) ^ asw) << 4);
            LDSM_X4(pf[0], pf[1], pf[2], pf[3], addrA);
#pragma unroll
            for (int p = 0; p < 8; p++) {
                uint32_t bvf[4];
                uint32_t addrB = vt + ((brow + (uint32_t)(p << 4)) << 8)
                                    + (((2u * s + bcsel) ^ bsw) << 4);
                LDSM_X4(bvf[0], bvf[1], bvf[2], bvf[3], addrB);
                mma_tf32(oacc[2 * p],     pf, bvf[0], bvf[1]);
                mma_tf32(oacc[2 * p + 1], pf, bvf[2], bvf[3]);
            }
        }
    }

    float inv0 = 1.0f / lrow[0];
    float inv1 = 1.0f / lrow[1];
    int row = q0 + (w << 4) + (lane >> 2);
#pragma unroll
    for (int nt = 0; nt < 16; nt++) {
        int col = h * HEAD_DIM + (nt << 3) + ((lane & 3) << 1);
        *(float2*)(O + (size_t)row * D_MODEL + col) =
            make_float2(round_tf32(oacc[nt][0] * inv0), round_tf32(oacc[nt][1] * inv0));
        *(float2*)(O + (size_t)(row + 8) * D_MODEL + col) =
            make_float2(round_tf32(oacc[nt][2] * inv1), round_tf32(oacc[nt][3] * inv1));
    }
}

// ---------------------------------------------------------------------------
extern "C" void kernel_launch(void* const* d_in, const int* in_sizes, int n_in,
                              void* d_out, int out_size)
{
    (void)in_sizes; (void)n_in; (void)out_size;
    const float* x  = (const float*)d_in[0];
    const float* fc = (const float*)d_in[1];
    const float* fs = (const float*)d_in[2];
    const float* wq = (const float*)d_in[4];
    const float* wk = (const float*)d_in[5];
    const float* wv = (const float*)d_in[6];
    const float* wo = (const float*)d_in[7];
    float* out = (float*)d_out;

    float *Qp, *Kp, *Vp, *Ap, *Xp, *WT4p;
    cudaGetSymbolAddress((void**)&Qp,   g_Q);
    cudaGetSymbolAddress((void**)&Kp,   g_K);
    cudaGetSymbolAddress((void**)&Vp,   g_V);
    cudaGetSymbolAddress((void**)&Ap,   g_A);
    cudaGetSymbolAddress((void**)&Xp,   g_X);
    cudaGetSymbolAddress((void**)&WT4p, g_WT4);

    cudaFuncSetAttribute(gemm_tc_kernel, cudaFuncAttributeMaxDynamicSharedMemorySize,
                         GEMM_SMEM_BYTES);
    cudaFuncSetAttribute(attn_tc_kernel, cudaFuncAttributeMaxDynamicSharedMemorySize,
                         ATT_SMEM_BYTES);

    const size_t WSZ = (size_t)D_MODEL * D_MODEL;

    // fused prep: round(x) + 4 transposes
    prep_kernel<<<dim3(64, 64, 5), dim3(32, 8)>>>(x, wq, wk, wv, wo, Xp, WT4p);

    // fused QKV GEMM with fused RoPE on Q,K: N=6144 -> 24 x-tiles
    gemm_tc_kernel<<<dim3(24, 16), 256, GEMM_SMEM_BYTES>>>(
        Xp, WT4p, Qp, Kp, Vp, fc, fs, 8, 2);

    attn_tc_kernel<<<dim3(SEQ / 128, N_HEADS), 256, ATT_SMEM_BYTES>>>(Qp, Kp, Vp, Ap);

    // output projection: N=2048 -> 8 x-tiles, no rope
    gemm_tc_kernel<<<dim3(8, 16), 256, GEMM_SMEM_BYTES>>>(
        Ap, WT4p + 3 * WSZ, out, out, out, fc, fs, 8, 0);
}

// round 7
// speedup vs baseline: 1.1371x; 1.1371x over previous
#include <cuda_runtime.h>
#include <cstdint>
#include <math.h>

#define D_MODEL 2048
#define SEQ     2048
#define N_HEADS 16
#define HEAD_DIM 128

// Scratch (no cudaMalloc allowed)
__device__ float g_Q[SEQ * D_MODEL];
__device__ float g_K[SEQ * D_MODEL];
__device__ float g_Vt[D_MODEL * SEQ];   // V transposed: [channel][seq]
__device__ float g_A[SEQ * D_MODEL];
__device__ float g_X[SEQ * D_MODEL];
__device__ float g_WT4[4 * D_MODEL * D_MODEL];

// ---------------------------------------------------------------------------
// helpers
// ---------------------------------------------------------------------------
static __device__ __forceinline__ uint32_t smem_u32(const void* p) {
    return (uint32_t)__cvta_generic_to_shared(p);
}

#define LDSM_X4(r0, r1, r2, r3, addr) \
    asm volatile("ldmatrix.sync.aligned.m8n8.x4.shared.b16 {%0,%1,%2,%3}, [%4];" \
                 : "=r"(r0), "=r"(r1), "=r"(r2), "=r"(r3) : "r"(addr))

static __device__ __forceinline__ void mma_tf32(
    float* c, const uint32_t* a, uint32_t b0, uint32_t b1)
{
    asm volatile(
        "mma.sync.aligned.m16n8k8.row.col.f32.tf32.tf32.f32 "
        "{%0,%1,%2,%3}, {%4,%5,%6,%7}, {%8,%9}, {%0,%1,%2,%3};"
        : "+f"(c[0]), "+f"(c[1]), "+f"(c[2]), "+f"(c[3])
        : "r"(a[0]), "r"(a[1]), "r"(a[2]), "r"(a[3]), "r"(b0), "r"(b1));
}

static __device__ __forceinline__ float round_tf32(float x) {
    uint32_t r;
    asm("cvt.rna.tf32.f32 %0, %1;" : "=r"(r) : "f"(x));
    return __uint_as_float(r);
}

static __device__ __forceinline__ void sts_tf32x2(uint32_t addr, float x, float y) {
    uint32_t a, b;
    asm("cvt.rna.tf32.f32 %0, %1;" : "=r"(a) : "f"(x));
    asm("cvt.rna.tf32.f32 %0, %1;" : "=r"(b) : "f"(y));
    asm volatile("st.shared.v2.b32 [%0], {%1, %2};"
                 :: "r"(addr), "r"(a), "r"(b) : "memory");
}

static __device__ __forceinline__ void cp_async16(uint32_t dst, const void* src) {
    asm volatile("cp.async.cg.shared.global [%0], [%1], 16;"
                 :: "r"(dst), "l"(src) : "memory");
}
#define CP_COMMIT() asm volatile("cp.async.commit_group;" ::: "memory")
#define CP_WAIT(n)  asm volatile("cp.async.wait_group %0;" :: "n"(n) : "memory")

// ---------------------------------------------------------------------------
// prep: z=0 round-copy x ; z=1..4 transpose+round wq/wk/wv/wo into WT slabs
// ---------------------------------------------------------------------------
__global__ __launch_bounds__(256) void prep_kernel(
    const float* __restrict__ x,
    const float* __restrict__ wq, const float* __restrict__ wk,
    const float* __restrict__ wv, const float* __restrict__ wo,
    float* __restrict__ X, float* __restrict__ WT)
{
    const size_t WSZ = (size_t)D_MODEL * D_MODEL;
    int z = blockIdx.z;
    if (z == 0) {
        int c = blockIdx.x * 32 + threadIdx.x;
#pragma unroll
        for (int i = 0; i < 4; i++) {
            int r = blockIdx.y * 32 + threadIdx.y + i * 8;
            X[(size_t)r * D_MODEL + c] = round_tf32(x[(size_t)r * D_MODEL + c]);
        }
        return;
    }
    const float* in = (z == 1) ? wq : (z == 2) ? wk : (z == 3) ? wv : wo;
    float* out = WT + (size_t)(z - 1) * WSZ;

    __shared__ float tile[32][33];
    int xx = blockIdx.x * 32 + threadIdx.x;
    int yy = blockIdx.y * 32 + threadIdx.y;
#pragma unroll
    for (int i = 0; i < 32; i += 8)
        tile[threadIdx.y + i][threadIdx.x] = in[(size_t)(yy + i) * D_MODEL + xx];
    __syncthreads();
    xx = blockIdx.y * 32 + threadIdx.x;
    yy = blockIdx.x * 32 + threadIdx.y;
#pragma unroll
    for (int i = 0; i < 32; i += 8)
        out[(size_t)(yy + i) * D_MODEL + xx] = round_tf32(tile[threadIdx.x][threadIdx.y + i]);
}

// ---------------------------------------------------------------------------
// tf32 mma.sync GEMM: CTA 128x256, warp 64x64, BK=32, 3-stage cp.async.
// mat = bx / tiles_per_mat -> C0/C1/C2.
//   mat < rope_mats : apply RoPE then round to tf32 (Q, K)
//   mat == vt_mat   : store transposed+rounded into C (Vt[channel][seq])
//   else            : plain fp32 store (final output)
// ---------------------------------------------------------------------------
#define GSTAGES 3
#define GSTAGE_BYTES 49152
#define GEMM_SMEM_BYTES (GSTAGES * GSTAGE_BYTES)

__global__ __launch_bounds__(256, 1) void gemm_tc_kernel(
    const float* __restrict__ A, const float* __restrict__ BT,
    float* __restrict__ C0, float* __restrict__ C1, float* __restrict__ C2,
    const float* __restrict__ fc, const float* __restrict__ fs,
    int tiles_per_mat, int rope_mats, int vt_mat)
{
    extern __shared__ char smc[];
    uint32_t sb = smem_u32(smc);

    int t    = threadIdx.x;
    int lane = t & 31;
    int wid  = t >> 5;
    int row0 = blockIdx.y << 7;
    int bx   = blockIdx.x;
    int mat  = bx / tiles_per_mat;
    int col0 = (bx % tiles_per_mat) << 8;
    float* C = (mat == 0) ? C0 : (mat == 1 ? C1 : C2);
    const float* Arow = A + (size_t)row0 * D_MODEL;
    const float* Brow = BT + ((size_t)bx << 8) * D_MODEL;
    bool dorope = (mat < rope_mats);
    bool dovt   = (mat == vt_mat);

    int wm = (wid >> 2) << 6;
    int wn = (wid & 3) << 6;

    float acc[4][8][4];
#pragma unroll
    for (int i = 0; i < 4; i++)
#pragma unroll
        for (int j = 0; j < 8; j++)
#pragma unroll
            for (int q = 0; q < 4; q++) acc[i][j][q] = 0.0f;

    uint32_t arow  = (uint32_t)(wm + (lane & 7) + ((lane >> 3) & 1) * 8);
    uint32_t acsel = (uint32_t)((lane >> 4) & 1);
    uint32_t brow  = (uint32_t)(wn + (lane & 7) + ((lane >> 4) & 1) * 8);
    uint32_t bcsel = (uint32_t)((lane >> 3) & 1);
    uint32_t asw7  = arow & 7;
    uint32_t bsw7  = brow & 7;

    const int cr = t >> 3;
    const int cc = t & 7;
    const uint32_t csw = (uint32_t)((cr << 7) + ((cc ^ (cr & 7)) << 4));

    const int NCHUNK = D_MODEL / 32;

#pragma unroll
    for (int pc = 0; pc < 2; pc++) {
        uint32_t abuf = sb + (uint32_t)pc * GSTAGE_BYTES;
        uint32_t bbuf = abuf + 16384u;
        const float* Ag = Arow + (pc << 5);
        const float* Bg = Brow + (pc << 5);
#pragma unroll
        for (int i = 0; i < 4; i++)
            cp_async16(abuf + csw + (uint32_t)(i << 12),
                       Ag + (size_t)(cr + (i << 5)) * D_MODEL + (cc << 2));
#pragma unroll
        for (int i = 0; i < 8; i++)
            cp_async16(bbuf + csw + (uint32_t)(i << 12),
                       Bg + (size_t)(cr + (i << 5)) * D_MODEL + (cc << 2));
        CP_COMMIT();
    }

    int stage = 0;
#pragma unroll 1
    for (int c = 0; c < NCHUNK; c++) {
        if (c + 1 < NCHUNK) CP_WAIT(1);
        else                CP_WAIT(0);
        __syncthreads();

        uint32_t ab = sb + (uint32_t)stage * GSTAGE_BYTES;
        uint32_t bb = ab + 16384u;

#pragma unroll
        for (int s = 0; s < 4; s++) {
            uint32_t af[4][4], bf[4][4];
#pragma unroll
            for (int mt = 0; mt < 4; mt++) {
                uint32_t addr = ab + ((arow + mt * 16) << 7)
                                   + (((2u * s + acsel) ^ asw7) << 4);
                LDSM_X4(af[mt][0], af[mt][1], af[mt][2], af[mt][3], addr);
            }
#pragma unroll
            for (int p = 0; p < 4; p++) {
                uint32_t addr = bb + ((brow + p * 16) << 7)
                                   + (((2u * s + bcsel) ^ bsw7) << 4);
                LDSM_X4(bf[p][0], bf[p][1], bf[p][2], bf[p][3], addr);
            }
#pragma unroll
            for (int mt = 0; mt < 4; mt++)
#pragma unroll
                for (int nt = 0; nt < 8; nt++)
                    mma_tf32(acc[mt][nt], af[mt],
                             bf[nt >> 1][(nt & 1) * 2],
                             bf[nt >> 1][(nt & 1) * 2 + 1]);
        }

        __syncthreads();

        if (c + 2 < NCHUNK) {
            int nc = c + 2;
            uint32_t abuf = sb + (uint32_t)((stage + 2) % GSTAGES) * GSTAGE_BYTES;
            uint32_t bbuf = abuf + 16384u;
            const float* Ag = Arow + (nc << 5);
            const float* Bg = Brow + (nc << 5);
#pragma unroll
            for (int i = 0; i < 4; i++)
                cp_async16(abuf + csw + (uint32_t)(i << 12),
                           Ag + (size_t)(cr + (i << 5)) * D_MODEL + (cc << 2));
#pragma unroll
            for (int i = 0; i < 8; i++)
                cp_async16(bbuf + csw + (uint32_t)(i << 12),
                           Bg + (size_t)(cr + (i << 5)) * D_MODEL + (cc << 2));
        }
        CP_COMMIT();

        stage++;
        if (stage == GSTAGES) stage = 0;
    }

    // ---- epilogue ----
    if (dovt) {
        // V: store transposed + tf32-rounded: Vt[ce][re] = acc
#pragma unroll
        for (int mt = 0; mt < 4; mt++) {
            int re = row0 + wm + mt * 16 + (lane >> 2);
#pragma unroll
            for (int nt = 0; nt < 8; nt++) {
                int ce = col0 + wn + nt * 8 + ((lane & 3) << 1);
                C[(size_t)ce * SEQ + re]           = round_tf32(acc[mt][nt][0]);
                C[(size_t)(ce + 1) * SEQ + re]     = round_tf32(acc[mt][nt][1]);
                C[(size_t)ce * SEQ + re + 8]       = round_tf32(acc[mt][nt][2]);
                C[(size_t)(ce + 1) * SEQ + re + 8] = round_tf32(acc[mt][nt][3]);
            }
        }
    } else {
#pragma unroll
        for (int mt = 0; mt < 4; mt++) {
            int re = row0 + wm + mt * 16 + (lane >> 2);
#pragma unroll
            for (int nt = 0; nt < 8; nt++) {
                int ce = col0 + wn + nt * 8 + ((lane & 3) << 1);
                float2 v0 = make_float2(acc[mt][nt][0], acc[mt][nt][1]);
                float2 v1 = make_float2(acc[mt][nt][2], acc[mt][nt][3]);
                if (dorope) {
                    int pidx = (ce & 127) >> 1;
                    float c0 = fc[(size_t)re * 64 + pidx];
                    float s0 = fs[(size_t)re * 64 + pidx];
                    float c1 = fc[(size_t)(re + 8) * 64 + pidx];
                    float s1 = fs[(size_t)(re + 8) * 64 + pidx];
                    v0 = make_float2(round_tf32(v0.x * c0 - v0.y * s0),
                                     round_tf32(v0.x * s0 + v0.y * c0));
                    v1 = make_float2(round_tf32(v1.x * c1 - v1.y * s1),
                                     round_tf32(v1.x * s1 + v1.y * c1));
                }
                *(float2*)(C + (size_t)re * D_MODEL + ce)       = v0;
                *(float2*)(C + (size_t)(re + 8) * D_MODEL + ce) = v1;
            }
        }
    }
}

// ---------------------------------------------------------------------------
// FlashAttention-2 on tf32 mma.sync, v2: cp.async double-buffered K/Vt tiles.
// Q, K in gmem are tf32-rounded (RoPE epilogue); Vt is tf32-rounded transposed.
// Grid (16, 16), 256 threads / 8 warps; warp = 16 Q rows; KV tile = 64 keys.
// SMEM: Kbuf[2][64][128] (pitch 512B) | Vtbuf[2][128][64] (pitch 256B) | P.
// ---------------------------------------------------------------------------
#define ATT_SMEM_BYTES (160 * 1024)

__global__ __launch_bounds__(256, 1) void attn_tc_kernel(
    const float* __restrict__ Q, const float* __restrict__ K,
    const float* __restrict__ Vt, float* __restrict__ O)
{
    extern __shared__ char smc[];
    uint32_t sb = smem_u32(smc);
    const uint32_t ps = sb + 131072u;

    int t    = threadIdx.x;
    int lane = t & 31;
    int w    = t >> 5;
    int qt   = (int)gridDim.x - 1 - (int)blockIdx.x;
    int h    = blockIdx.y;
    int q0   = qt << 7;

    uint32_t arow  = (uint32_t)((lane & 7) + ((lane >> 3) & 1) * 8);
    uint32_t acsel = (uint32_t)((lane >> 4) & 1);
    uint32_t brow  = (uint32_t)((lane & 7) + ((lane >> 4) & 1) * 8);
    uint32_t bcsel = (uint32_t)((lane >> 3) & 1);
    uint32_t asw   = arow & 7;
    uint32_t bsw   = brow & 7;

    const float* Kh  = K  + h * HEAD_DIM;
    const float* Vth = Vt + (size_t)(h * HEAD_DIM) * SEQ;

    // ---- stage Q (128x128 tf32) via cp.async into [0,64KB), build A-frags ----
    uint32_t qf[16][4];
    {
        const float* Qg = Q + (size_t)q0 * D_MODEL + h * HEAD_DIM;
#pragma unroll
        for (int i = 0; i < 16; i++) {
            int lin = t + (i << 8);
            int r   = lin >> 5;
            int c   = lin & 31;
            cp_async16(sb + (r << 9) + (((uint32_t)c ^ (r & 7)) << 4),
                       Qg + (size_t)r * D_MODEL + (c << 2));
        }
        CP_COMMIT();
        CP_WAIT(0);
        __syncthreads();
        uint32_t qrow = arow + (uint32_t)(w << 4);
        uint32_t qsw  = qrow & 7;
#pragma unroll
        for (int s = 0; s < 16; s++) {
            uint32_t addr = sb + (qrow << 9) + (((2u * s + acsel) ^ qsw) << 4);
            LDSM_X4(qf[s][0], qf[s][1], qf[s][2], qf[s][3], addr);
        }
        __syncthreads();   // qf read everywhere before K tile 0 overwrites staging
    }

    float oacc[16][4];
#pragma unroll
    for (int i = 0; i < 16; i++)
#pragma unroll
        for (int j = 0; j < 4; j++) oacc[i][j] = 0.0f;
    float mrow[2] = {-1e30f, -1e30f};
    float lrow[2] = {0.0f, 0.0f};

    const float scale = 0.08838834764831845f;
    const int   ktmax = 2 * qt + 1;
    const uint32_t pbase = ps + (uint32_t)(w << 12);

    // K tile copy: 8 chunks/thread; Vt tile copy: 8 chunks/thread
    const int kr = t >> 2;          // not used; keep simple per-loop mapping

    // prologue: tile 0 into buf 0
    {
        const float* Kg = Kh + 0;
#pragma unroll
        for (int i = 0; i < 8; i++) {
            int lin = t + (i << 8);
            int r   = lin >> 5;
            int c   = lin & 31;
            cp_async16(sb + (r << 9) + (((uint32_t)c ^ (r & 7)) << 4),
                       Kg + (size_t)r * D_MODEL + (c << 2));
        }
#pragma unroll
        for (int i = 0; i < 8; i++) {
            int lin = t + (i << 8);
            int r   = lin >> 4;       // d 0..127
            int c   = lin & 15;       // 16B chunk 0..15
            cp_async16(sb + 65536u + (r << 8) + (((uint32_t)c ^ (r & 7)) << 4),
                       Vth + (size_t)r * SEQ + (c << 2));
        }
        CP_COMMIT();
    }

#pragma unroll 1
    for (int kt = 0; kt <= ktmax; kt++) {
        int buf = kt & 1;
        if (kt < ktmax) {
            int nb = (kt + 1) & 1;
            const float* Kg  = Kh  + ((size_t)(kt + 1) << 6) * D_MODEL;
            const float* Vtg = Vth + ((size_t)(kt + 1) << 6);
#pragma unroll
            for (int i = 0; i < 8; i++) {
                int lin = t + (i << 8);
                int r   = lin >> 5;
                int c   = lin & 31;
                cp_async16(sb + (uint32_t)nb * 32768u + (r << 9)
                              + (((uint32_t)c ^ (r & 7)) << 4),
                           Kg + (size_t)r * D_MODEL + (c << 2));
            }
#pragma unroll
            for (int i = 0; i < 8; i++) {
                int lin = t + (i << 8);
                int r   = lin >> 4;
                int c   = lin & 15;
                cp_async16(sb + 65536u + (uint32_t)nb * 32768u + (r << 8)
                              + (((uint32_t)c ^ (r & 7)) << 4),
                           Vtg + (size_t)r * SEQ + (c << 2));
            }
            CP_COMMIT();
            CP_WAIT(1);
        } else {
            CP_WAIT(0);
        }
        __syncthreads();

        uint32_t kb = sb + (uint32_t)buf * 32768u;
        uint32_t vb = sb + 65536u + (uint32_t)buf * 32768u;

        // ---- S = Q @ K^T ----
        float sacc[8][4];
#pragma unroll
        for (int nt = 0; nt < 8; nt++)
#pragma unroll
            for (int e = 0; e < 4; e++) sacc[nt][e] = 0.0f;

#pragma unroll
        for (int s = 0; s < 16; s++) {
            uint32_t bf[4][4];
#pragma unroll
            for (int p = 0; p < 4; p++) {
                uint32_t addr = kb + ((brow + (uint32_t)(p << 4)) << 9)
                                   + (((2u * s + bcsel) ^ bsw) << 4);
                LDSM_X4(bf[p][0], bf[p][1], bf[p][2], bf[p][3], addr);
            }
#pragma unroll
            for (int nt = 0; nt < 8; nt++)
                mma_tf32(sacc[nt], qf[s],
                         bf[nt >> 1][(nt & 1) * 2],
                         bf[nt >> 1][(nt & 1) * 2 + 1]);
        }

        // ---- scale + causal mask ----
        bool need_mask = (kt >= 2 * qt);
        int grow = q0 + (w << 4) + (lane >> 2);
#pragma unroll
        for (int nt = 0; nt < 8; nt++) {
#pragma unroll
            for (int e = 0; e < 4; e++) {
                float v = sacc[nt][e] * scale;
                if (need_mask) {
                    int row = grow + (e >> 1) * 8;
                    int col = (kt << 6) + (nt << 3) + ((lane & 3) << 1) + (e & 1);
                    if (col > row) v = -1e30f;
                }
                sacc[nt][e] = v;
            }
        }

        // ---- online softmax ----
        float alpha[2];
#pragma unroll
        for (int half = 0; half < 2; half++) {
            float mx = -1e30f;
#pragma unroll
            for (int nt = 0; nt < 8; nt++)
                mx = fmaxf(mx, fmaxf(sacc[nt][2 * half], sacc[nt][2 * half + 1]));
            mx = fmaxf(mx, __shfl_xor_sync(0xffffffffu, mx, 1));
            mx = fmaxf(mx, __shfl_xor_sync(0xffffffffu, mx, 2));
            float mnew = fmaxf(mrow[half], mx);
            alpha[half] = __expf(mrow[half] - mnew);
            float sum = 0.0f;
#pragma unroll
            for (int nt = 0; nt < 8; nt++) {
                float p0 = __expf(sacc[nt][2 * half]     - mnew);
                float p1 = __expf(sacc[nt][2 * half + 1] - mnew);
                sacc[nt][2 * half]     = p0;
                sacc[nt][2 * half + 1] = p1;
                sum += p0 + p1;
            }
            sum += __shfl_xor_sync(0xffffffffu, sum, 1);
            sum += __shfl_xor_sync(0xffffffffu, sum, 2);
            lrow[half] = lrow[half] * alpha[half] + sum;
            mrow[half] = mnew;
        }
#pragma unroll
        for (int nt = 0; nt < 16; nt++) {
            oacc[nt][0] *= alpha[0];  oacc[nt][1] *= alpha[0];
            oacc[nt][2] *= alpha[1];  oacc[nt][3] *= alpha[1];
        }

        // ---- stash P into per-warp smem (A-frag layout conversion) ----
        {
            uint32_t prow0 = (uint32_t)(lane >> 2);
            uint32_t prow1 = prow0 + 8;
#pragma unroll
            for (int nt = 0; nt < 8; nt++) {
                uint32_t col   = (uint32_t)((nt << 3) + ((lane & 3) << 1));
                uint32_t chunk = col >> 2;
                uint32_t coff  = (col & 3) << 2;
                sts_tf32x2(pbase + (prow0 << 8) + ((chunk ^ (prow0 & 7)) << 4) + coff,
                           sacc[nt][0], sacc[nt][1]);
                sts_tf32x2(pbase + (prow1 << 8) + ((chunk ^ (prow1 & 7)) << 4) + coff,
                           sacc[nt][2], sacc[nt][3]);
            }
        }
        __syncwarp();

        // ---- O += P @ V ----
#pragma unroll
        for (int s = 0; s < 8; s++) {
            uint32_t pf[4];
            uint32_t addrA = pbase + (arow << 8) + (((2u * s + acsel) ^ asw) << 4);
            LDSM_X4(pf[0], pf[1], pf[2], pf[3], addrA);
#pragma unroll
            for (int p = 0; p < 8; p++) {
                uint32_t bvf[4];
                uint32_t addrB = vb + ((brow + (uint32_t)(p << 4)) << 8)
                                    + (((2u * s + bcsel) ^ bsw) << 4);
                LDSM_X4(bvf[0], bvf[1], bvf[2], bvf[3], addrB);
                mma_tf32(oacc[2 * p],     pf, bvf[0], bvf[1]);
                mma_tf32(oacc[2 * p + 1], pf, bvf[2], bvf[3]);
            }
        }
        __syncthreads();   // buffer kt&1 fully consumed before next issue
    }

    float inv0 = 1.0f / lrow[0];
    float inv1 = 1.0f / lrow[1];
    int row = q0 + (w << 4) + (lane >> 2);
#pragma unroll
    for (int nt = 0; nt < 16; nt++) {
        int col = h * HEAD_DIM + (nt << 3) + ((lane & 3) << 1);
        *(float2*)(O + (size_t)row * D_MODEL + col) =
            make_float2(round_tf32(oacc[nt][0] * inv0), round_tf32(oacc[nt][1] * inv0));
        *(float2*)(O + (size_t)(row + 8) * D_MODEL + col) =
            make_float2(round_tf32(oacc[nt][2] * inv1), round_tf32(oacc[nt][3] * inv1));
    }
}

// ---------------------------------------------------------------------------
extern "C" void kernel_launch(void* const* d_in, const int* in_sizes, int n_in,
                              void* d_out, int out_size)
{
    (void)in_sizes; (void)n_in; (void)out_size;
    const float* x  = (const float*)d_in[0];
    const float* fc = (const float*)d_in[1];
    const float* fs = (const float*)d_in[2];
    const float* wq = (const float*)d_in[4];
    const float* wk = (const float*)d_in[5];
    const float* wv = (const float*)d_in[6];
    const float* wo = (const float*)d_in[7];
    float* out = (float*)d_out;

    float *Qp, *Kp, *Vtp, *Ap, *Xp, *WT4p;
    cudaGetSymbolAddress((void**)&Qp,   g_Q);
    cudaGetSymbolAddress((void**)&Kp,   g_K);
    cudaGetSymbolAddress((void**)&Vtp,  g_Vt);
    cudaGetSymbolAddress((void**)&Ap,   g_A);
    cudaGetSymbolAddress((void**)&Xp,   g_X);
    cudaGetSymbolAddress((void**)&WT4p, g_WT4);

    cudaFuncSetAttribute(gemm_tc_kernel, cudaFuncAttributeMaxDynamicSharedMemorySize,
                         GEMM_SMEM_BYTES);
    cudaFuncSetAttribute(attn_tc_kernel, cudaFuncAttributeMaxDynamicSharedMemorySize,
                         ATT_SMEM_BYTES);

    const size_t WSZ = (size_t)D_MODEL * D_MODEL;

    prep_kernel<<<dim3(64, 64, 5), dim3(32, 8)>>>(x, wq, wk, wv, wo, Xp, WT4p);

    // fused QKV GEMM: RoPE+round on Q,K; transposed+rounded store for V
    gemm_tc_kernel<<<dim3(24, 16), 256, GEMM_SMEM_BYTES>>>(
        Xp, WT4p, Qp, Kp, Vtp, fc, fs, 8, 2, 2);

    attn_tc_kernel<<<dim3(SEQ / 128, N_HEADS), 256, ATT_SMEM_BYTES>>>(Qp, Kp, Vtp, Ap);

    // output projection (plain fp32 store)
    gemm_tc_kernel<<<dim3(8, 16), 256, GEMM_SMEM_BYTES>>>(
        Ap, WT4p + 3 * WSZ, out, out, out, fc, fs, 8, 0, -1);
}

// round 8
// speedup vs baseline: 1.4376x; 1.2643x over previous
#include <cuda_runtime.h>
#include <cuda_fp16.h>
#include <cstdint>
#include <math.h>

#define D_MODEL 2048
#define SEQ     2048
#define N_HEADS 16
#define HEAD_DIM 128

// Scratch (no cudaMalloc allowed) — all intermediates fp16
__device__ __half g_Q[SEQ * D_MODEL];
__device__ __half g_K[SEQ * D_MODEL];
__device__ __half g_Vt[D_MODEL * SEQ];   // V transposed: [channel][seq]
__device__ __half g_A[SEQ * D_MODEL];
__device__ __half g_X[SEQ * D_MODEL];
__device__ __half g_WT4[4 * D_MODEL * D_MODEL];

// ---------------------------------------------------------------------------
// helpers
// ---------------------------------------------------------------------------
static __device__ __forceinline__ uint32_t smem_u32(const void* p) {
    return (uint32_t)__cvta_generic_to_shared(p);
}

#define LDSM_X4(r0, r1, r2, r3, addr) \
    asm volatile("ldmatrix.sync.aligned.m8n8.x4.shared.b16 {%0,%1,%2,%3}, [%4];" \
                 : "=r"(r0), "=r"(r1), "=r"(r2), "=r"(r3) : "r"(addr))

static __device__ __forceinline__ void mma_f16(
    float* c, const uint32_t* a, uint32_t b0, uint32_t b1)
{
    asm volatile(
        "mma.sync.aligned.m16n8k16.row.col.f32.f16.f16.f32 "
        "{%0,%1,%2,%3}, {%4,%5,%6,%7}, {%8,%9}, {%0,%1,%2,%3};"
        : "+f"(c[0]), "+f"(c[1]), "+f"(c[2]), "+f"(c[3])
        : "r"(a[0]), "r"(a[1]), "r"(a[2]), "r"(a[3]), "r"(b0), "r"(b1));
}

// pack two fp32 -> half2 bits (lo = first arg in memory order)
static __device__ __forceinline__ uint32_t pack_half2(float lo, float hi) {
    uint32_t r;
    asm("cvt.rn.f16x2.f32 %0, %1, %2;" : "=r"(r) : "f"(hi), "f"(lo));
    return r;
}

static __device__ __forceinline__ void cp_async16(uint32_t dst, const void* src) {
    asm volatile("cp.async.cg.shared.global [%0], [%1], 16;"
                 :: "r"(dst), "l"(src) : "memory");
}
#define CP_COMMIT() asm volatile("cp.async.commit_group;" ::: "memory")
#define CP_WAIT(n)  asm volatile("cp.async.wait_group %0;" :: "n"(n) : "memory")

// ---------------------------------------------------------------------------
// prep: z=0 convert x->fp16 ; z=1..4 transpose+convert wq/wk/wv/wo
// ---------------------------------------------------------------------------
__global__ __launch_bounds__(256) void prep_kernel(
    const float* __restrict__ x,
    const float* __restrict__ wq, const float* __restrict__ wk,
    const float* __restrict__ wv, const float* __restrict__ wo,
    __half* __restrict__ X, __half* __restrict__ WT)
{
    const size_t WSZ = (size_t)D_MODEL * D_MODEL;
    int z = blockIdx.z;
    if (z == 0) {
        int c = blockIdx.x * 32 + threadIdx.x;
#pragma unroll
        for (int i = 0; i < 4; i++) {
            int r = blockIdx.y * 32 + threadIdx.y + i * 8;
            X[(size_t)r * D_MODEL + c] = __float2half_rn(x[(size_t)r * D_MODEL + c]);
        }
        return;
    }
    const float* in = (z == 1) ? wq : (z == 2) ? wk : (z == 3) ? wv : wo;
    __half* out = WT + (size_t)(z - 1) * WSZ;

    __shared__ float tile[32][33];
    int xx = blockIdx.x * 32 + threadIdx.x;
    int yy = blockIdx.y * 32 + threadIdx.y;
#pragma unroll
    for (int i = 0; i < 32; i += 8)
        tile[threadIdx.y + i][threadIdx.x] = in[(size_t)(yy + i) * D_MODEL + xx];
    __syncthreads();
    xx = blockIdx.y * 32 + threadIdx.x;
    yy = blockIdx.x * 32 + threadIdx.y;
#pragma unroll
    for (int i = 0; i < 32; i += 8)
        out[(size_t)(yy + i) * D_MODEL + xx] = __float2half_rn(tile[threadIdx.x][threadIdx.y + i]);
}

// ---------------------------------------------------------------------------
// fp16 mma.sync GEMM: CTA 128x256, warp 64x64, BK=64 halfs, 3-stage cp.async.
// A[2048,2048]h, BT[nrows,2048]h (= B^T). Tiles: A 128x64h (128B pitch, 16KB),
// B 256x64h (128B pitch, 32KB). Swizzle: 16B-chunk c ^= (row&7).
// Epilogues: rope->fp16 (Q,K) | transposed fp16 (Vt) | plain fp32 (proj out).
// ---------------------------------------------------------------------------
#define GSTAGES 3
#define GSTAGE_BYTES 49152
#define GEMM_SMEM_BYTES (GSTAGES * GSTAGE_BYTES)

__global__ __launch_bounds__(256, 1) void gemm_tc_kernel(
    const __half* __restrict__ A, const __half* __restrict__ BT,
    __half* __restrict__ C0, __half* __restrict__ C1, __half* __restrict__ C2,
    float* __restrict__ Cf,
    const float* __restrict__ fc, const float* __restrict__ fs,
    int tiles_per_mat, int rope_mats, int vt_mat)
{
    extern __shared__ char smc[];
    uint32_t sb = smem_u32(smc);

    int t    = threadIdx.x;
    int lane = t & 31;
    int wid  = t >> 5;
    int row0 = blockIdx.y << 7;
    int bx   = blockIdx.x;
    int mat  = bx / tiles_per_mat;
    int col0 = (bx % tiles_per_mat) << 8;
    __half* C = (mat == 0) ? C0 : (mat == 1 ? C1 : C2);
    const __half* Arow = A + (size_t)row0 * D_MODEL;
    const __half* Brow = BT + ((size_t)bx << 8) * D_MODEL;
    bool dorope = (mat < rope_mats);
    bool dovt   = (mat == vt_mat);

    int wm = (wid >> 2) << 6;
    int wn = (wid & 3) << 6;

    float acc[4][8][4];
#pragma unroll
    for (int i = 0; i < 4; i++)
#pragma unroll
        for (int j = 0; j < 8; j++)
#pragma unroll
            for (int q = 0; q < 4; q++) acc[i][j][q] = 0.0f;

    uint32_t arow  = (uint32_t)(wm + (lane & 15));
    uint32_t acsel = (uint32_t)((lane >> 4) & 1);
    uint32_t brow  = (uint32_t)(wn + (lane & 7) + ((lane >> 4) & 1) * 8);
    uint32_t bcsel = (uint32_t)((lane >> 3) & 1);
    uint32_t asw7  = arow & 7;
    uint32_t bsw7  = brow & 7;

    // copy geometry (BK=64 halfs = 8 x 16B chunks per row)
    const int car = t >> 1;                 // A row 0..127
    const int cac = (t & 1) << 2;           // A chunk base 0 or 4
    const int cbr = t;                      // B row 0..255

    const int NCHUNK = D_MODEL / 64;   // 32

#pragma unroll
    for (int pc = 0; pc < 2; pc++) {
        uint32_t abuf = sb + (uint32_t)pc * GSTAGE_BYTES;
        uint32_t bbuf = abuf + 16384u;
        const __half* Ag = Arow + (pc << 6);
        const __half* Bg = Brow + (pc << 6);
#pragma unroll
        for (int i = 0; i < 4; i++) {
            int c = cac + i;
            cp_async16(abuf + (car << 7) + ((uint32_t)(c ^ (car & 7)) << 4),
                       Ag + (size_t)car * D_MODEL + (c << 3));
        }
#pragma unroll
        for (int i = 0; i < 8; i++)
            cp_async16(bbuf + (cbr << 7) + ((uint32_t)(i ^ (cbr & 7)) << 4),
                       Bg + (size_t)cbr * D_MODEL + (i << 3));
        CP_COMMIT();
    }

    int stage = 0;
#pragma unroll 1
    for (int c = 0; c < NCHUNK; c++) {
        if (c + 1 < NCHUNK) CP_WAIT(1);
        else                CP_WAIT(0);
        __syncthreads();

        uint32_t ab = sb + (uint32_t)stage * GSTAGE_BYTES;
        uint32_t bb = ab + 16384u;

#pragma unroll
        for (int s = 0; s < 4; s++) {
            uint32_t af[4][4], bf[4][4];
#pragma unroll
            for (int mt = 0; mt < 4; mt++) {
                uint32_t addr = ab + ((arow + mt * 16) << 7)
                                   + (((2u * s + acsel) ^ asw7) << 4);
                LDSM_X4(af[mt][0], af[mt][1], af[mt][2], af[mt][3], addr);
            }
#pragma unroll
            for (int p = 0; p < 4; p++) {
                uint32_t addr = bb + ((brow + p * 16) << 7)
                                   + (((2u * s + bcsel) ^ bsw7) << 4);
                LDSM_X4(bf[p][0], bf[p][1], bf[p][2], bf[p][3], addr);
            }
#pragma unroll
            for (int mt = 0; mt < 4; mt++)
#pragma unroll
                for (int nt = 0; nt < 8; nt++)
                    mma_f16(acc[mt][nt], af[mt],
                            bf[nt >> 1][(nt & 1) * 2],
                            bf[nt >> 1][(nt & 1) * 2 + 1]);
        }

        __syncthreads();

        if (c + 2 < NCHUNK) {
            int nc = c + 2;
            uint32_t abuf = sb + (uint32_t)((stage + 2) % GSTAGES) * GSTAGE_BYTES;
            uint32_t bbuf = abuf + 16384u;
            const __half* Ag = Arow + (nc << 6);
            const __half* Bg = Brow + (nc << 6);
#pragma unroll
            for (int i = 0; i < 4; i++) {
                int cc = cac + i;
                cp_async16(abuf + (car << 7) + ((uint32_t)(cc ^ (car & 7)) << 4),
                           Ag + (size_t)car * D_MODEL + (cc << 3));
            }
#pragma unroll
            for (int i = 0; i < 8; i++)
                cp_async16(bbuf + (cbr << 7) + ((uint32_t)(i ^ (cbr & 7)) << 4),
                           Bg + (size_t)cbr * D_MODEL + (i << 3));
        }
        CP_COMMIT();

        stage++;
        if (stage == GSTAGES) stage = 0;
    }

    // ---- epilogue ----
    if (Cf != nullptr) {
#pragma unroll
        for (int mt = 0; mt < 4; mt++) {
            int re = row0 + wm + mt * 16 + (lane >> 2);
#pragma unroll
            for (int nt = 0; nt < 8; nt++) {
                int ce = col0 + wn + nt * 8 + ((lane & 3) << 1);
                *(float2*)(Cf + (size_t)re * D_MODEL + ce) =
                    make_float2(acc[mt][nt][0], acc[mt][nt][1]);
                *(float2*)(Cf + (size_t)(re + 8) * D_MODEL + ce) =
                    make_float2(acc[mt][nt][2], acc[mt][nt][3]);
            }
        }
    } else if (dovt) {
#pragma unroll
        for (int mt = 0; mt < 4; mt++) {
            int re = row0 + wm + mt * 16 + (lane >> 2);
#pragma unroll
            for (int nt = 0; nt < 8; nt++) {
                int ce = col0 + wn + nt * 8 + ((lane & 3) << 1);
                C[(size_t)ce * SEQ + re]           = __float2half_rn(acc[mt][nt][0]);
                C[(size_t)(ce + 1) * SEQ + re]     = __float2half_rn(acc[mt][nt][1]);
                C[(size_t)ce * SEQ + re + 8]       = __float2half_rn(acc[mt][nt][2]);
                C[(size_t)(ce + 1) * SEQ + re + 8] = __float2half_rn(acc[mt][nt][3]);
            }
        }
    } else {
#pragma unroll
        for (int mt = 0; mt < 4; mt++) {
            int re = row0 + wm + mt * 16 + (lane >> 2);
#pragma unroll
            for (int nt = 0; nt < 8; nt++) {
                int ce = col0 + wn + nt * 8 + ((lane & 3) << 1);
                float2 v0 = make_float2(acc[mt][nt][0], acc[mt][nt][1]);
                float2 v1 = make_float2(acc[mt][nt][2], acc[mt][nt][3]);
                if (dorope) {
                    int pidx = (ce & 127) >> 1;
                    float c0 = fc[(size_t)re * 64 + pidx];
                    float s0 = fs[(size_t)re * 64 + pidx];
                    float c1 = fc[(size_t)(re + 8) * 64 + pidx];
                    float s1 = fs[(size_t)(re + 8) * 64 + pidx];
                    v0 = make_float2(v0.x * c0 - v0.y * s0, v0.x * s0 + v0.y * c0);
                    v1 = make_float2(v1.x * c1 - v1.y * s1, v1.x * s1 + v1.y * c1);
                }
                *(uint32_t*)(C + (size_t)re * D_MODEL + ce)       = pack_half2(v0.x, v0.y);
                *(uint32_t*)(C + (size_t)(re + 8) * D_MODEL + ce) = pack_half2(v1.x, v1.y);
            }
        }
    }
}

// ---------------------------------------------------------------------------
// FlashAttention-2 on fp16 mma.sync, cp.async double-buffered K/Vt tiles.
// Grid (16, 16), 256 threads / 8 warps; warp = 16 Q rows; KV tile = 64 keys.
// SMEM: Kbuf[2][64rows][256B] at 0 (Q staged here first), Vt[2][128][128B]
// at 32K, P[8][16][128B] at 64K. Total 80KB.
// ---------------------------------------------------------------------------
#define ATT_SMEM_BYTES (80 * 1024)

__global__ __launch_bounds__(256, 1) void attn_tc_kernel(
    const __half* __restrict__ Q, const __half* __restrict__ K,
    const __half* __restrict__ Vt, __half* __restrict__ O)
{
    extern __shared__ char smc[];
    uint32_t sb = smem_u32(smc);

    int t    = threadIdx.x;
    int lane = t & 31;
    int w    = t >> 5;
    int qt   = (int)gridDim.x - 1 - (int)blockIdx.x;
    int h    = blockIdx.y;
    int q0   = qt << 7;

    uint32_t arow  = (uint32_t)(lane & 15);
    uint32_t acsel = (uint32_t)((lane >> 4) & 1);
    uint32_t brow  = (uint32_t)((lane & 7) + ((lane >> 4) & 1) * 8);
    uint32_t bcsel = (uint32_t)((lane >> 3) & 1);
    uint32_t asw   = arow & 7;
    uint32_t bsw   = brow & 7;

    const __half* Kh  = K  + h * HEAD_DIM;
    const __half* Vth = Vt + (size_t)(h * HEAD_DIM) * SEQ;

    // ---- stage Q (128x128h, 256B pitch) into [0,32K), build A-frags ----
    uint32_t qf[8][4];
    {
        const __half* Qg = Q + (size_t)q0 * D_MODEL + h * HEAD_DIM;
#pragma unroll
        for (int i = 0; i < 8; i++) {
            int lin = t + (i << 8);
            int r   = lin >> 4;
            int c   = lin & 15;
            cp_async16(sb + (r << 8) + ((uint32_t)(c ^ (r & 7)) << 4),
                       Qg + (size_t)r * D_MODEL + (c << 3));
        }
        CP_COMMIT();
        CP_WAIT(0);
        __syncthreads();
        uint32_t qrow = arow + (uint32_t)(w << 4);
        uint32_t qsw  = qrow & 7;
#pragma unroll
        for (int s = 0; s < 8; s++) {
            uint32_t addr = sb + (qrow << 8) + (((2u * s + acsel) ^ qsw) << 4);
            LDSM_X4(qf[s][0], qf[s][1], qf[s][2], qf[s][3], addr);
        }
        __syncthreads();   // qf built before K tile 0 overwrites staging
    }

    float oacc[16][4];
#pragma unroll
    for (int i = 0; i < 16; i++)
#pragma unroll
        for (int j = 0; j < 4; j++) oacc[i][j] = 0.0f;
    float mrow[2] = {-1e30f, -1e30f};
    float lrow[2] = {0.0f, 0.0f};

    const float scale = 0.08838834764831845f;
    const int   ktmax = 2 * qt + 1;
    const uint32_t pbase = sb + 65536u + (uint32_t)(w << 11);

    // prologue: tile 0 into buf 0
    {
#pragma unroll
        for (int i = 0; i < 4; i++) {
            int lin = t + (i << 8);
            int r   = lin >> 4;       // key 0..63
            int c   = lin & 15;
            cp_async16(sb + (r << 8) + ((uint32_t)(c ^ (r & 7)) << 4),
                       Kh + (size_t)r * D_MODEL + (c << 3));
        }
#pragma unroll
        for (int i = 0; i < 4; i++) {
            int lin = t + (i << 8);
            int r   = lin >> 3;       // d 0..127
            int c   = lin & 7;
            cp_async16(sb + 32768u + (r << 7) + ((uint32_t)(c ^ (r & 7)) << 4),
                       Vth + (size_t)r * SEQ + (c << 3));
        }
        CP_COMMIT();
    }

#pragma unroll 1
    for (int kt = 0; kt <= ktmax; kt++) {
        int buf = kt & 1;
        if (kt < ktmax) {
            int nb = (kt + 1) & 1;
            const __half* Kg  = Kh  + ((size_t)(kt + 1) << 6) * D_MODEL;
            const __half* Vtg = Vth + ((size_t)(kt + 1) << 6);
#pragma unroll
            for (int i = 0; i < 4; i++) {
                int lin = t + (i << 8);
                int r   = lin >> 4;
                int c   = lin & 15;
                cp_async16(sb + (uint32_t)nb * 16384u + (r << 8)
                              + ((uint32_t)(c ^ (r & 7)) << 4),
                           Kg + (size_t)r * D_MODEL + (c << 3));
            }
#pragma unroll
            for (int i = 0; i < 4; i++) {
                int lin = t + (i << 8);
                int r   = lin >> 3;
                int c   = lin & 7;
                cp_async16(sb + 32768u + (uint32_t)nb * 16384u + (r << 7)
                              + ((uint32_t)(c ^ (r & 7)) << 4),
                           Vtg + (size_t)r * SEQ + (c << 3));
            }
            CP_COMMIT();
            CP_WAIT(1);
        } else {
            CP_WAIT(0);
        }
        __syncthreads();

        uint32_t kb = sb + (uint32_t)buf * 16384u;
        uint32_t vb = sb + 32768u + (uint32_t)buf * 16384u;

        // ---- S = Q @ K^T : warp m16 x n64, 8 k16-steps ----
        float sacc[8][4];
#pragma unroll
        for (int nt = 0; nt < 8; nt++)
#pragma unroll
            for (int e = 0; e < 4; e++) sacc[nt][e] = 0.0f;

#pragma unroll
        for (int s = 0; s < 8; s++) {
            uint32_t bf[4][4];
#pragma unroll
            for (int p = 0; p < 4; p++) {
                uint32_t addr = kb + ((brow + (uint32_t)(p << 4)) << 8)
                                   + (((2u * s + bcsel) ^ bsw) << 4);
                LDSM_X4(bf[p][0], bf[p][1], bf[p][2], bf[p][3], addr);
            }
#pragma unroll
            for (int nt = 0; nt < 8; nt++)
                mma_f16(sacc[nt], qf[s],
                        bf[nt >> 1][(nt & 1) * 2],
                        bf[nt >> 1][(nt & 1) * 2 + 1]);
        }

        // ---- scale + causal mask ----
        bool need_mask = (kt >= 2 * qt);
        int grow = q0 + (w << 4) + (lane >> 2);
#pragma unroll
        for (int nt = 0; nt < 8; nt++) {
#pragma unroll
            for (int e = 0; e < 4; e++) {
                float v = sacc[nt][e] * scale;
                if (need_mask) {
                    int row = grow + (e >> 1) * 8;
                    int col = (kt << 6) + (nt << 3) + ((lane & 3) << 1) + (e & 1);
                    if (col > row) v = -1e30f;
                }
                sacc[nt][e] = v;
            }
        }

        // ---- online softmax ----
        float alpha[2];
#pragma unroll
        for (int half = 0; half < 2; half++) {
            float mx = -1e30f;
#pragma unroll
            for (int nt = 0; nt < 8; nt++)
                mx = fmaxf(mx, fmaxf(sacc[nt][2 * half], sacc[nt][2 * half + 1]));
            mx = fmaxf(mx, __shfl_xor_sync(0xffffffffu, mx, 1));
            mx = fmaxf(mx, __shfl_xor_sync(0xffffffffu, mx, 2));
            float mnew = fmaxf(mrow[half], mx);
            alpha[half] = __expf(mrow[half] - mnew);
            float sum = 0.0f;
#pragma unroll
            for (int nt = 0; nt < 8; nt++) {
                float p0 = __expf(sacc[nt][2 * half]     - mnew);
                float p1 = __expf(sacc[nt][2 * half + 1] - mnew);
                sacc[nt][2 * half]     = p0;
                sacc[nt][2 * half + 1] = p1;
                sum += p0 + p1;
            }
            sum += __shfl_xor_sync(0xffffffffu, sum, 1);
            sum += __shfl_xor_sync(0xffffffffu, sum, 2);
            lrow[half] = lrow[half] * alpha[half] + sum;
            mrow[half] = mnew;
        }
#pragma unroll
        for (int nt = 0; nt < 16; nt++) {
            oacc[nt][0] *= alpha[0];  oacc[nt][1] *= alpha[0];
            oacc[nt][2] *= alpha[1];  oacc[nt][3] *= alpha[1];
        }

        // ---- stash P as fp16 (A-frag layout conversion via smem) ----
        {
            uint32_t prow0 = (uint32_t)(lane >> 2);
            uint32_t prow1 = prow0 + 8;
            uint32_t psw   = prow0 & 7;
            uint32_t coff  = (uint32_t)((lane & 3) << 2);
#pragma unroll
            for (int nt = 0; nt < 8; nt++) {
                uint32_t chunk = ((uint32_t)nt ^ psw) << 4;
                asm volatile("st.shared.b32 [%0], %1;"
                             :: "r"(pbase + (prow0 << 7) + chunk + coff),
                                "r"(pack_half2(sacc[nt][0], sacc[nt][1])) : "memory");
                asm volatile("st.shared.b32 [%0], %1;"
                             :: "r"(pbase + (prow1 << 7) + chunk + coff),
                                "r"(pack_half2(sacc[nt][2], sacc[nt][3])) : "memory");
            }
        }
        __syncwarp();

        // ---- O += P @ V : 4 k16-steps over 64 keys ----
#pragma unroll
        for (int s = 0; s < 4; s++) {
            uint32_t pf[4];
            uint32_t addrA = pbase + (arow << 7) + (((2u * s + acsel) ^ asw) << 4);
            LDSM_X4(pf[0], pf[1], pf[2], pf[3], addrA);
#pragma unroll
            for (int p = 0; p < 8; p++) {
                uint32_t bvf[4];
                uint32_t addrB = vb + ((brow + (uint32_t)(p << 4)) << 7)
                                    + (((2u * s + bcsel) ^ bsw) << 4);
                LDSM_X4(bvf[0], bvf[1], bvf[2], bvf[3], addrB);
                mma_f16(oacc[2 * p],     pf, bvf[0], bvf[1]);
                mma_f16(oacc[2 * p + 1], pf, bvf[2], bvf[3]);
            }
        }
        __syncthreads();
    }

    float inv0 = 1.0f / lrow[0];
    float inv1 = 1.0f / lrow[1];
    int row = q0 + (w << 4) + (lane >> 2);
#pragma unroll
    for (int nt = 0; nt < 16; nt++) {
        int col = h * HEAD_DIM + (nt << 3) + ((lane & 3) << 1);
        *(uint32_t*)(O + (size_t)row * D_MODEL + col) =
            pack_half2(oacc[nt][0] * inv0, oacc[nt][1] * inv0);
        *(uint32_t*)(O + (size_t)(row + 8) * D_MODEL + col) =
            pack_half2(oacc[nt][2] * inv1, oacc[nt][3] * inv1);
    }
}

// ---------------------------------------------------------------------------
extern "C" void kernel_launch(void* const* d_in, const int* in_sizes, int n_in,
                              void* d_out, int out_size)
{
    (void)in_sizes; (void)n_in; (void)out_size;
    const float* x  = (const float*)d_in[0];
    const float* fc = (const float*)d_in[1];
    const float* fs = (const float*)d_in[2];
    const float* wq = (const float*)d_in[4];
    const float* wk = (const float*)d_in[5];
    const float* wv = (const float*)d_in[6];
    const float* wo = (const float*)d_in[7];
    float* out = (float*)d_out;

    __half *Qp, *Kp, *Vtp, *Ap, *Xp, *WT4p;
    cudaGetSymbolAddress((void**)&Qp,   g_Q);
    cudaGetSymbolAddress((void**)&Kp,   g_K);
    cudaGetSymbolAddress((void**)&Vtp,  g_Vt);
    cudaGetSymbolAddress((void**)&Ap,   g_A);
    cudaGetSymbolAddress((void**)&Xp,   g_X);
    cudaGetSymbolAddress((void**)&WT4p, g_WT4);

    cudaFuncSetAttribute(gemm_tc_kernel, cudaFuncAttributeMaxDynamicSharedMemorySize,
                         GEMM_SMEM_BYTES);
    cudaFuncSetAttribute(attn_tc_kernel, cudaFuncAttributeMaxDynamicSharedMemorySize,
                         ATT_SMEM_BYTES);

    const size_t WSZ = (size_t)D_MODEL * D_MODEL;

    prep_kernel<<<dim3(64, 64, 5), dim3(32, 8)>>>(x, wq, wk, wv, wo, Xp, WT4p);

    // fused QKV GEMM: RoPE->fp16 on Q,K; transposed fp16 store for V
    gemm_tc_kernel<<<dim3(24, 16), 256, GEMM_SMEM_BYTES>>>(
        Xp, WT4p, Qp, Kp, Vtp, nullptr, fc, fs, 8, 2, 2);

    attn_tc_kernel<<<dim3(SEQ / 128, N_HEADS), 256, ATT_SMEM_BYTES>>>(Qp, Kp, Vtp, Ap);

    // output projection -> fp32 out
    gemm_tc_kernel<<<dim3(8, 16), 256, GEMM_SMEM_BYTES>>>(
        Ap, WT4p + 3 * WSZ, nullptr, nullptr, nullptr, out, fc, fs, 8, 0, -1);
}

// round 9
// speedup vs baseline: 1.4390x; 1.0009x over previous
#include <cuda_runtime.h>
#include <cuda_fp16.h>
#include <cstdint>
#include <math.h>

#define D_MODEL 2048
#define SEQ     2048
#define N_HEADS 16
#define HEAD_DIM 128

__device__ __half g_Q[SEQ * D_MODEL];
__device__ __half g_K[SEQ * D_MODEL];
__device__ __half g_Vt[D_MODEL * SEQ];
__device__ __half g_A[SEQ * D_MODEL];
__device__ __half g_X[SEQ * D_MODEL];
__device__ __half g_WT4[4 * D_MODEL * D_MODEL];

// ---------------------------------------------------------------------------
static __device__ __forceinline__ uint32_t smem_u32(const void* p) {
    return (uint32_t)__cvta_generic_to_shared(p);
}

#define LDSM_X4(r0, r1, r2, r3, addr) \
    asm volatile("ldmatrix.sync.aligned.m8n8.x4.shared.b16 {%0,%1,%2,%3}, [%4];" \
                 : "=r"(r0), "=r"(r1), "=r"(r2), "=r"(r3) : "r"(addr))

static __device__ __forceinline__ void mma_f16(
    float* c, const uint32_t* a, uint32_t b0, uint32_t b1)
{
    asm volatile(
        "mma.sync.aligned.m16n8k16.row.col.f32.f16.f16.f32 "
        "{%0,%1,%2,%3}, {%4,%5,%6,%7}, {%8,%9}, {%0,%1,%2,%3};"
        : "+f"(c[0]), "+f"(c[1]), "+f"(c[2]), "+f"(c[3])
        : "r"(a[0]), "r"(a[1]), "r"(a[2]), "r"(a[3]), "r"(b0), "r"(b1));
}

static __device__ __forceinline__ uint32_t pack_half2(float lo, float hi) {
    uint32_t r;
    asm("cvt.rn.f16x2.f32 %0, %1, %2;" : "=r"(r) : "f"(hi), "f"(lo));
    return r;
}

static __device__ __forceinline__ void cp_async16(uint32_t dst, const void* src) {
    asm volatile("cp.async.cg.shared.global [%0], [%1], 16;"
                 :: "r"(dst), "l"(src) : "memory");
}
#define CP_COMMIT() asm volatile("cp.async.commit_group;" ::: "memory")
#define CP_WAIT(n)  asm volatile("cp.async.wait_group %0;" :: "n"(n) : "memory")

// ---------------------------------------------------------------------------
// prep: z=0 convert x->fp16 ; z=1..4 transpose+convert wq/wk/wv/wo
// ---------------------------------------------------------------------------
__global__ __launch_bounds__(256) void prep_kernel(
    const float* __restrict__ x,
    const float* __restrict__ wq, const float* __restrict__ wk,
    const float* __restrict__ wv, const float* __restrict__ wo,
    __half* __restrict__ X, __half* __restrict__ WT)
{
    const size_t WSZ = (size_t)D_MODEL * D_MODEL;
    int z = blockIdx.z;
    if (z == 0) {
        int c = blockIdx.x * 32 + threadIdx.x;
#pragma unroll
        for (int i = 0; i < 4; i++) {
            int r = blockIdx.y * 32 + threadIdx.y + i * 8;
            X[(size_t)r * D_MODEL + c] = __float2half_rn(x[(size_t)r * D_MODEL + c]);
        }
        return;
    }
    const float* in = (z == 1) ? wq : (z == 2) ? wk : (z == 3) ? wv : wo;
    __half* out = WT + (size_t)(z - 1) * WSZ;

    __shared__ float tile[32][33];
    int xx = blockIdx.x * 32 + threadIdx.x;
    int yy = blockIdx.y * 32 + threadIdx.y;
#pragma unroll
    for (int i = 0; i < 32; i += 8)
        tile[threadIdx.y + i][threadIdx.x] = in[(size_t)(yy + i) * D_MODEL + xx];
    __syncthreads();
    xx = blockIdx.y * 32 + threadIdx.x;
    yy = blockIdx.x * 32 + threadIdx.y;
#pragma unroll
    for (int i = 0; i < 32; i += 8)
        out[(size_t)(yy + i) * D_MODEL + xx] = __float2half_rn(tile[threadIdx.x][threadIdx.y + i]);
}

// ---------------------------------------------------------------------------
// fp16 mma.sync GEMM: CTA 128x256, warp 64x64, BK=64, 4-stage cp.async.
// ---------------------------------------------------------------------------
#define GSTAGES 4
#define GSTAGE_BYTES 49152
#define GEMM_SMEM_BYTES (GSTAGES * GSTAGE_BYTES)

__global__ __launch_bounds__(256, 1) void gemm_tc_kernel(
    const __half* __restrict__ A, const __half* __restrict__ BT,
    __half* __restrict__ C0, __half* __restrict__ C1, __half* __restrict__ C2,
    float* __restrict__ Cf,
    const float* __restrict__ fc, const float* __restrict__ fs,
    int tiles_per_mat, int rope_mats, int vt_mat)
{
    extern __shared__ char smc[];
    uint32_t sb = smem_u32(smc);

    int t    = threadIdx.x;
    int lane = t & 31;
    int wid  = t >> 5;
    int row0 = blockIdx.y << 7;
    int bx   = blockIdx.x;
    int mat  = bx / tiles_per_mat;
    int col0 = (bx % tiles_per_mat) << 8;
    __half* C = (mat == 0) ? C0 : (mat == 1 ? C1 : C2);
    const __half* Arow = A + (size_t)row0 * D_MODEL;
    const __half* Brow = BT + ((size_t)bx << 8) * D_MODEL;
    bool dorope = (mat < rope_mats);
    bool dovt   = (mat == vt_mat);

    int wm = (wid >> 2) << 6;
    int wn = (wid & 3) << 6;

    float acc[4][8][4];
#pragma unroll
    for (int i = 0; i < 4; i++)
#pragma unroll
        for (int j = 0; j < 8; j++)
#pragma unroll
            for (int q = 0; q < 4; q++) acc[i][j][q] = 0.0f;

    uint32_t arow  = (uint32_t)(wm + (lane & 15));
    uint32_t acsel = (uint32_t)((lane >> 4) & 1);
    uint32_t brow  = (uint32_t)(wn + (lane & 7) + ((lane >> 4) & 1) * 8);
    uint32_t bcsel = (uint32_t)((lane >> 3) & 1);
    uint32_t asw7  = arow & 7;
    uint32_t bsw7  = brow & 7;

    const int car = t >> 1;
    const int cac = (t & 1) << 2;
    const int cbr = t;

    const int NCHUNK = D_MODEL / 64;   // 32

    // prologue: stages 0,1,2
#pragma unroll
    for (int pc = 0; pc < 3; pc++) {
        uint32_t abuf = sb + (uint32_t)pc * GSTAGE_BYTES;
        uint32_t bbuf = abuf + 16384u;
        const __half* Ag = Arow + (pc << 6);
        const __half* Bg = Brow + (pc << 6);
#pragma unroll
        for (int i = 0; i < 4; i++) {
            int c = cac + i;
            cp_async16(abuf + (car << 7) + ((uint32_t)(c ^ (car & 7)) << 4),
                       Ag + (size_t)car * D_MODEL + (c << 3));
        }
#pragma unroll
        for (int i = 0; i < 8; i++)
            cp_async16(bbuf + (cbr << 7) + ((uint32_t)(i ^ (cbr & 7)) << 4),
                       Bg + (size_t)cbr * D_MODEL + (i << 3));
        CP_COMMIT();
    }

    int stage = 0;
#pragma unroll 1
    for (int c = 0; c < NCHUNK; c++) {
        CP_WAIT(2);           // oldest group (chunk c) complete
        __syncthreads();

        uint32_t ab = sb + (uint32_t)stage * GSTAGE_BYTES;
        uint32_t bb = ab + 16384u;

#pragma unroll
        for (int s = 0; s < 4; s++) {
            uint32_t af[4][4], bf[4][4];
#pragma unroll
            for (int mt = 0; mt < 4; mt++) {
                uint32_t addr = ab + ((arow + mt * 16) << 7)
                                   + (((2u * s + acsel) ^ asw7) << 4);
                LDSM_X4(af[mt][0], af[mt][1], af[mt][2], af[mt][3], addr);
            }
#pragma unroll
            for (int p = 0; p < 4; p++) {
                uint32_t addr = bb + ((brow + p * 16) << 7)
                                   + (((2u * s + bcsel) ^ bsw7) << 4);
                LDSM_X4(bf[p][0], bf[p][1], bf[p][2], bf[p][3], addr);
            }
#pragma unroll
            for (int mt = 0; mt < 4; mt++)
#pragma unroll
                for (int nt = 0; nt < 8; nt++)
                    mma_f16(acc[mt][nt], af[mt],
                            bf[nt >> 1][(nt & 1) * 2],
                            bf[nt >> 1][(nt & 1) * 2 + 1]);
        }

        __syncthreads();

        if (c + 3 < NCHUNK) {
            int nc = c + 3;
            uint32_t abuf = sb + (uint32_t)((stage + 3) & 3) * GSTAGE_BYTES;
            uint32_t bbuf = abuf + 16384u;
            const __half* Ag = Arow + (nc << 6);
            const __half* Bg = Brow + (nc << 6);
#pragma unroll
            for (int i = 0; i < 4; i++) {
                int cc = cac + i;
                cp_async16(abuf + (car << 7) + ((uint32_t)(cc ^ (car & 7)) << 4),
                           Ag + (size_t)car * D_MODEL + (cc << 3));
            }
#pragma unroll
            for (int i = 0; i < 8; i++)
                cp_async16(bbuf + (cbr << 7) + ((uint32_t)(i ^ (cbr & 7)) << 4),
                           Bg + (size_t)cbr * D_MODEL + (i << 3));
        }
        CP_COMMIT();   // unconditional: keeps exactly 3 groups outstanding

        stage = (stage + 1) & 3;
    }

    // ---- epilogue ----
    if (Cf != nullptr) {
#pragma unroll
        for (int mt = 0; mt < 4; mt++) {
            int re = row0 + wm + mt * 16 + (lane >> 2);
#pragma unroll
            for (int nt = 0; nt < 8; nt++) {
                int ce = col0 + wn + nt * 8 + ((lane & 3) << 1);
                *(float2*)(Cf + (size_t)re * D_MODEL + ce) =
                    make_float2(acc[mt][nt][0], acc[mt][nt][1]);
                *(float2*)(Cf + (size_t)(re + 8) * D_MODEL + ce) =
                    make_float2(acc[mt][nt][2], acc[mt][nt][3]);
            }
        }
    } else if (dovt) {
#pragma unroll
        for (int mt = 0; mt < 4; mt++) {
            int re = row0 + wm + mt * 16 + (lane >> 2);
#pragma unroll
            for (int nt = 0; nt < 8; nt++) {
                int ce = col0 + wn + nt * 8 + ((lane & 3) << 1);
                C[(size_t)ce * SEQ + re]           = __float2half_rn(acc[mt][nt][0]);
                C[(size_t)(ce + 1) * SEQ + re]     = __float2half_rn(acc[mt][nt][1]);
                C[(size_t)ce * SEQ + re + 8]       = __float2half_rn(acc[mt][nt][2]);
                C[(size_t)(ce + 1) * SEQ + re + 8] = __float2half_rn(acc[mt][nt][3]);
            }
        }
    } else {
#pragma unroll
        for (int mt = 0; mt < 4; mt++) {
            int re = row0 + wm + mt * 16 + (lane >> 2);
#pragma unroll
            for (int nt = 0; nt < 8; nt++) {
                int ce = col0 + wn + nt * 8 + ((lane & 3) << 1);
                float2 v0 = make_float2(acc[mt][nt][0], acc[mt][nt][1]);
                float2 v1 = make_float2(acc[mt][nt][2], acc[mt][nt][3]);
                if (dorope) {
                    int pidx = (ce & 127) >> 1;
                    float c0 = fc[(size_t)re * 64 + pidx];
                    float s0 = fs[(size_t)re * 64 + pidx];
                    float c1 = fc[(size_t)(re + 8) * 64 + pidx];
                    float s1 = fs[(size_t)(re + 8) * 64 + pidx];
                    v0 = make_float2(v0.x * c0 - v0.y * s0, v0.x * s0 + v0.y * c0);
                    v1 = make_float2(v1.x * c1 - v1.y * s1, v1.x * s1 + v1.y * c1);
                }
                *(uint32_t*)(C + (size_t)re * D_MODEL + ce)       = pack_half2(v0.x, v0.y);
                *(uint32_t*)(C + (size_t)(re + 8) * D_MODEL + ce) = pack_half2(v1.x, v1.y);
            }
        }
    }
}

// ---------------------------------------------------------------------------
// FlashAttention-2 fp16, 3-buffer K/Vt ring, prefetch 2 tiles ahead.
// SMEM: K[3][16KB] at 0, Vt[3][16KB] at 48K, P[8][2KB] at 96K. Total 112KB.
// ---------------------------------------------------------------------------
#define ATT_SMEM_BYTES (112 * 1024)

__global__ __launch_bounds__(256, 1) void attn_tc_kernel(
    const __half* __restrict__ Q, const __half* __restrict__ K,
    const __half* __restrict__ Vt, __half* __restrict__ O)
{
    extern __shared__ char smc[];
    uint32_t sb = smem_u32(smc);
    const uint32_t VBASE = sb + 49152u;
    const uint32_t PBASE = sb + 98304u;

    int t    = threadIdx.x;
    int lane = t & 31;
    int w    = t >> 5;
    int qt   = (int)gridDim.x - 1 - (int)blockIdx.x;
    int h    = blockIdx.y;
    int q0   = qt << 7;

    uint32_t arow  = (uint32_t)(lane & 15);
    uint32_t acsel = (uint32_t)((lane >> 4) & 1);
    uint32_t brow  = (uint32_t)((lane & 7) + ((lane >> 4) & 1) * 8);
    uint32_t bcsel = (uint32_t)((lane >> 3) & 1);
    uint32_t asw   = arow & 7;
    uint32_t bsw   = brow & 7;

    const __half* Kh  = K  + h * HEAD_DIM;
    const __half* Vth = Vt + (size_t)(h * HEAD_DIM) * SEQ;

    // ---- stage Q (128x128h, 256B pitch) into [0,32K), build A-frags ----
    uint32_t qf[8][4];
    {
        const __half* Qg = Q + (size_t)q0 * D_MODEL + h * HEAD_DIM;
#pragma unroll
        for (int i = 0; i < 8; i++) {
            int lin = t + (i << 8);
            int r   = lin >> 4;
            int c   = lin & 15;
            cp_async16(sb + (r << 8) + ((uint32_t)(c ^ (r & 7)) << 4),
                       Qg + (size_t)r * D_MODEL + (c << 3));
        }
        CP_COMMIT();
        CP_WAIT(0);
        __syncthreads();
        uint32_t qrow = arow + (uint32_t)(w << 4);
        uint32_t qsw  = qrow & 7;
#pragma unroll
        for (int s = 0; s < 8; s++) {
            uint32_t addr = sb + (qrow << 8) + (((2u * s + acsel) ^ qsw) << 4);
            LDSM_X4(qf[s][0], qf[s][1], qf[s][2], qf[s][3], addr);
        }
        __syncthreads();
    }

    float oacc[16][4];
#pragma unroll
    for (int i = 0; i < 16; i++)
#pragma unroll
        for (int j = 0; j < 4; j++) oacc[i][j] = 0.0f;
    float mrow[2] = {-1e30f, -1e30f};
    float lrow[2] = {0.0f, 0.0f};

    const float scale = 0.08838834764831845f;
    const int   ktmax = 2 * qt + 1;
    const uint32_t pbase = PBASE + (uint32_t)(w << 11);

    // tile loader: K tile 64x256B, Vt tile 128x128B into ring slot
    auto issue_tile = [&](int kt) {
        uint32_t slot = (uint32_t)(kt % 3);
        const __half* Kg  = Kh  + ((size_t)kt << 6) * D_MODEL;
        const __half* Vtg = Vth + ((size_t)kt << 6);
#pragma unroll
        for (int i = 0; i < 4; i++) {
            int lin = t + (i << 8);
            int r   = lin >> 4;
            int c   = lin & 15;
            cp_async16(sb + slot * 16384u + (r << 8) + ((uint32_t)(c ^ (r & 7)) << 4),
                       Kg + (size_t)r * D_MODEL + (c << 3));
        }
#pragma unroll
        for (int i = 0; i < 4; i++) {
            int lin = t + (i << 8);
            int r   = lin >> 3;
            int c   = lin & 7;
            cp_async16(VBASE + slot * 16384u + (r << 7) + ((uint32_t)(c ^ (r & 7)) << 4),
                       Vtg + (size_t)r * SEQ + (c << 3));
        }
    };

    // prologue: tiles 0,1 (ktmax >= 1 always)
    issue_tile(0); CP_COMMIT();
    issue_tile(1); CP_COMMIT();

#pragma unroll 1
    for (int kt = 0; kt <= ktmax; kt++) {
        if (kt + 2 <= ktmax) issue_tile(kt + 2);
        CP_COMMIT();          // unconditional: group count invariant
        CP_WAIT(2);           // tile kt ready
        __syncthreads();

        uint32_t slot = (uint32_t)(kt % 3);
        uint32_t kb = sb + slot * 16384u;
        uint32_t vb = VBASE + slot * 16384u;

        // ---- S = Q @ K^T ----
        float sacc[8][4];
#pragma unroll
        for (int nt = 0; nt < 8; nt++)
#pragma unroll
            for (int e = 0; e < 4; e++) sacc[nt][e] = 0.0f;

#pragma unroll
        for (int s = 0; s < 8; s++) {
            uint32_t bf[4][4];
#pragma unroll
            for (int p = 0; p < 4; p++) {
                uint32_t addr = kb + ((brow + (uint32_t)(p << 4)) << 8)
                                   + (((2u * s + bcsel) ^ bsw) << 4);
                LDSM_X4(bf[p][0], bf[p][1], bf[p][2], bf[p][3], addr);
            }
#pragma unroll
            for (int nt = 0; nt < 8; nt++)
                mma_f16(sacc[nt], qf[s],
                        bf[nt >> 1][(nt & 1) * 2],
                        bf[nt >> 1][(nt & 1) * 2 + 1]);
        }

        // ---- scale + causal mask ----
        bool need_mask = (kt >= 2 * qt);
        int grow = q0 + (w << 4) + (lane >> 2);
#pragma unroll
        for (int nt = 0; nt < 8; nt++) {
#pragma unroll
            for (int e = 0; e < 4; e++) {
                float v = sacc[nt][e] * scale;
                if (need_mask) {
                    int row = grow + (e >> 1) * 8;
                    int col = (kt << 6) + (nt << 3) + ((lane & 3) << 1) + (e & 1);
                    if (col > row) v = -1e30f;
                }
                sacc[nt][e] = v;
            }
        }

        // ---- online softmax ----
        float alpha[2];
#pragma unroll
        for (int half = 0; half < 2; half++) {
            float mx = -1e30f;
#pragma unroll
            for (int nt = 0; nt < 8; nt++)
                mx = fmaxf(mx, fmaxf(sacc[nt][2 * half], sacc[nt][2 * half + 1]));
            mx = fmaxf(mx, __shfl_xor_sync(0xffffffffu, mx, 1));
            mx = fmaxf(mx, __shfl_xor_sync(0xffffffffu, mx, 2));
            float mnew = fmaxf(mrow[half], mx);
            alpha[half] = __expf(mrow[half] - mnew);
            float sum = 0.0f;
#pragma unroll
            for (int nt = 0; nt < 8; nt++) {
                float p0 = __expf(sacc[nt][2 * half]     - mnew);
                float p1 = __expf(sacc[nt][2 * half + 1] - mnew);
                sacc[nt][2 * half]     = p0;
                sacc[nt][2 * half + 1] = p1;
                sum += p0 + p1;
            }
            sum += __shfl_xor_sync(0xffffffffu, sum, 1);
            sum += __shfl_xor_sync(0xffffffffu, sum, 2);
            lrow[half] = lrow[half] * alpha[half] + sum;
            mrow[half] = mnew;
        }
#pragma unroll
        for (int nt = 0; nt < 16; nt++) {
            oacc[nt][0] *= alpha[0];  oacc[nt][1] *= alpha[0];
            oacc[nt][2] *= alpha[1];  oacc[nt][3] *= alpha[1];
        }

        // ---- stash P as fp16 ----
        {
            uint32_t prow0 = (uint32_t)(lane >> 2);
            uint32_t prow1 = prow0 + 8;
            uint32_t psw   = prow0 & 7;
            uint32_t coff  = (uint32_t)((lane & 3) << 2);
#pragma unroll
            for (int nt = 0; nt < 8; nt++) {
                uint32_t chunk = ((uint32_t)nt ^ psw) << 4;
                asm volatile("st.shared.b32 [%0], %1;"
                             :: "r"(pbase + (prow0 << 7) + chunk + coff),
                                "r"(pack_half2(sacc[nt][0], sacc[nt][1])) : "memory");
                asm volatile("st.shared.b32 [%0], %1;"
                             :: "r"(pbase + (prow1 << 7) + chunk + coff),
                                "r"(pack_half2(sacc[nt][2], sacc[nt][3])) : "memory");
            }
        }
        __syncwarp();

        // ---- O += P @ V ----
#pragma unroll
        for (int s = 0; s < 4; s++) {
            uint32_t pf[4];
            uint32_t addrA = pbase + (arow << 7) + (((2u * s + acsel) ^ asw) << 4);
            LDSM_X4(pf[0], pf[1], pf[2], pf[3], addrA);
#pragma unroll
            for (int p = 0; p < 8; p++) {
                uint32_t bvf[4];
                uint32_t addrB = vb + ((brow + (uint32_t)(p << 4)) << 7)
                                    + (((2u * s + bcsel) ^ bsw) << 4);
                LDSM_X4(bvf[0], bvf[1], bvf[2], bvf[3], addrB);
                mma_f16(oacc[2 * p],     pf, bvf[0], bvf[1]);
                mma_f16(oacc[2 * p + 1], pf, bvf[2], bvf[3]);
            }
        }
        __syncthreads();
    }

    float inv0 = 1.0f / lrow[0];
    float inv1 = 1.0f / lrow[1];
    int row = q0 + (w << 4) + (lane >> 2);
#pragma unroll
    for (int nt = 0; nt < 16; nt++) {
        int col = h * HEAD_DIM + (nt << 3) + ((lane & 3) << 1);
        *(uint32_t*)(O + (size_t)row * D_MODEL + col) =
            pack_half2(oacc[nt][0] * inv0, oacc[nt][1] * inv0);
        *(uint32_t*)(O + (size_t)(row + 8) * D_MODEL + col) =
            pack_half2(oacc[nt][2] * inv1, oacc[nt][3] * inv1);
    }
}

// ---------------------------------------------------------------------------
extern "C" void kernel_launch(void* const* d_in, const int* in_sizes, int n_in,
                              void* d_out, int out_size)
{
    (void)in_sizes; (void)n_in; (void)out_size;
    const float* x  = (const float*)d_in[0];
    const float* fc = (const float*)d_in[1];
    const float* fs = (const float*)d_in[2];
    const float* wq = (const float*)d_in[4];
    const float* wk = (const float*)d_in[5];
    const float* wv = (const float*)d_in[6];
    const float* wo = (const float*)d_in[7];
    float* out = (float*)d_out;

    __half *Qp, *Kp, *Vtp, *Ap, *Xp, *WT4p;
    cudaGetSymbolAddress((void**)&Qp,   g_Q);
    cudaGetSymbolAddress((void**)&Kp,   g_K);
    cudaGetSymbolAddress((void**)&Vtp,  g_Vt);
    cudaGetSymbolAddress((void**)&Ap,   g_A);
    cudaGetSymbolAddress((void**)&Xp,   g_X);
    cudaGetSymbolAddress((void**)&WT4p, g_WT4);

    cudaFuncSetAttribute(gemm_tc_kernel, cudaFuncAttributeMaxDynamicSharedMemorySize,
                         GEMM_SMEM_BYTES);
    cudaFuncSetAttribute(attn_tc_kernel, cudaFuncAttributeMaxDynamicSharedMemorySize,
                         ATT_SMEM_BYTES);

    const size_t WSZ = (size_t)D_MODEL * D_MODEL;

    prep_kernel<<<dim3(64, 64, 5), dim3(32, 8)>>>(x, wq, wk, wv, wo, Xp, WT4p);

    gemm_tc_kernel<<<dim3(24, 16), 256, GEMM_SMEM_BYTES>>>(
        Xp, WT4p, Qp, Kp, Vtp, nullptr, fc, fs, 8, 2, 2);

    attn_tc_kernel<<<dim3(SEQ / 128, N_HEADS), 256, ATT_SMEM_BYTES>>>(Qp, Kp, Vtp, Ap);

    gemm_tc_kernel<<<dim3(8, 16), 256, GEMM_SMEM_BYTES>>>(
        Ap, WT4p + 3 * WSZ, nullptr, nullptr, nullptr, out, fc, fs, 8, 0, -1);
}

// round 10
// speedup vs baseline: 2.0134x; 1.3992x over previous
#include <cuda_runtime.h>
#include <cuda_fp16.h>
#include <cstdint>
#include <math.h>

#define D_MODEL 2048
#define SEQ     2048
#define N_HEADS 16
#define HEAD_DIM 128

__device__ __half g_Q[SEQ * D_MODEL];
__device__ __half g_K[SEQ * D_MODEL];
__device__ __half g_Vt[D_MODEL * SEQ];
__device__ __half g_A[SEQ * D_MODEL];
__device__ __half g_X[SEQ * D_MODEL];
__device__ __half g_WT4[4 * D_MODEL * D_MODEL];

// ---------------------------------------------------------------------------
static __device__ __forceinline__ uint32_t smem_u32(const void* p) {
    return (uint32_t)__cvta_generic_to_shared(p);
}

#define LDSM_X4(r0, r1, r2, r3, addr) \
    asm volatile("ldmatrix.sync.aligned.m8n8.x4.shared.b16 {%0,%1,%2,%3}, [%4];" \
                 : "=r"(r0), "=r"(r1), "=r"(r2), "=r"(r3) : "r"(addr))

static __device__ __forceinline__ void mma_f16(
    float* c, const uint32_t* a, uint32_t b0, uint32_t b1)
{
    asm volatile(
        "mma.sync.aligned.m16n8k16.row.col.f32.f16.f16.f32 "
        "{%0,%1,%2,%3}, {%4,%5,%6,%7}, {%8,%9}, {%0,%1,%2,%3};"
        : "+f"(c[0]), "+f"(c[1]), "+f"(c[2]), "+f"(c[3])
        : "r"(a[0]), "r"(a[1]), "r"(a[2]), "r"(a[3]), "r"(b0), "r"(b1));
}

static __device__ __forceinline__ uint32_t pack_half2(float lo, float hi) {
    uint32_t r;
    asm("cvt.rn.f16x2.f32 %0, %1, %2;" : "=r"(r) : "f"(hi), "f"(lo));
    return r;
}

static __device__ __forceinline__ void cp_async16(uint32_t dst, const void* src) {
    asm volatile("cp.async.cg.shared.global [%0], [%1], 16;"
                 :: "r"(dst), "l"(src) : "memory");
}
#define CP_COMMIT() asm volatile("cp.async.commit_group;" ::: "memory")
#define CP_WAIT(n)  asm volatile("cp.async.wait_group %0;" :: "n"(n) : "memory")

// ---------------------------------------------------------------------------
// prep: z=0 convert x->fp16 ; z=1..4 transpose+convert wq/wk/wv/wo
// ---------------------------------------------------------------------------
__global__ __launch_bounds__(256) void prep_kernel(
    const float* __restrict__ x,
    const float* __restrict__ wq, const float* __restrict__ wk,
    const float* __restrict__ wv, const float* __restrict__ wo,
    __half* __restrict__ X, __half* __restrict__ WT)
{
    const size_t WSZ = (size_t)D_MODEL * D_MODEL;
    int z = blockIdx.z;
    if (z == 0) {
        int c = blockIdx.x * 32 + threadIdx.x;
#pragma unroll
        for (int i = 0; i < 4; i++) {
            int r = blockIdx.y * 32 + threadIdx.y + i * 8;
            X[(size_t)r * D_MODEL + c] = __float2half_rn(x[(size_t)r * D_MODEL + c]);
        }
        return;
    }
    const float* in = (z == 1) ? wq : (z == 2) ? wk : (z == 3) ? wv : wo;
    __half* out = WT + (size_t)(z - 1) * WSZ;

    __shared__ float tile[32][33];
    int xx = blockIdx.x * 32 + threadIdx.x;
    int yy = blockIdx.y * 32 + threadIdx.y;
#pragma unroll
    for (int i = 0; i < 32; i += 8)
        tile[threadIdx.y + i][threadIdx.x] = in[(size_t)(yy + i) * D_MODEL + xx];
    __syncthreads();
    xx = blockIdx.y * 32 + threadIdx.x;
    yy = blockIdx.x * 32 + threadIdx.y;
#pragma unroll
    for (int i = 0; i < 32; i += 8)
        out[(size_t)(yy + i) * D_MODEL + xx] = __float2half_rn(tile[threadIdx.x][threadIdx.y + i]);
}

// ---------------------------------------------------------------------------
// fp16 mma.sync GEMM: CTA 128x256, 512 threads / 16 warps (4x4),
// warp tile 32x64, BK=64, 4-stage cp.async pipeline.
// ---------------------------------------------------------------------------
#define GSTAGES 4
#define GSTAGE_BYTES 49152
#define GEMM_SMEM_BYTES (GSTAGES * GSTAGE_BYTES)

__global__ __launch_bounds__(512, 1) void gemm_tc_kernel(
    const __half* __restrict__ A, const __half* __restrict__ BT,
    __half* __restrict__ C0, __half* __restrict__ C1, __half* __restrict__ C2,
    float* __restrict__ Cf,
    const float* __restrict__ fc, const float* __restrict__ fs,
    int tiles_per_mat, int rope_mats, int vt_mat)
{
    extern __shared__ char smc[];
    uint32_t sb = smem_u32(smc);

    int t    = threadIdx.x;
    int lane = t & 31;
    int wid  = t >> 5;
    int row0 = blockIdx.y << 7;
    int bx   = blockIdx.x;
    int mat  = bx / tiles_per_mat;
    int col0 = (bx % tiles_per_mat) << 8;
    __half* C = (mat == 0) ? C0 : (mat == 1 ? C1 : C2);
    const __half* Arow = A + (size_t)row0 * D_MODEL;
    const __half* Brow = BT + ((size_t)bx << 8) * D_MODEL;
    bool dorope = (mat < rope_mats);
    bool dovt   = (mat == vt_mat);

    int wm = (wid >> 2) << 5;    // warp row: 0/32/64/96
    int wn = (wid & 3) << 6;     // warp col: 0/64/128/192

    float acc[2][8][4];
#pragma unroll
    for (int i = 0; i < 2; i++)
#pragma unroll
        for (int j = 0; j < 8; j++)
#pragma unroll
            for (int q = 0; q < 4; q++) acc[i][j][q] = 0.0f;

    uint32_t arow  = (uint32_t)(wm + (lane & 15));
    uint32_t acsel = (uint32_t)((lane >> 4) & 1);
    uint32_t brow  = (uint32_t)(wn + (lane & 7) + ((lane >> 4) & 1) * 8);
    uint32_t bcsel = (uint32_t)((lane >> 3) & 1);
    uint32_t asw7  = arow & 7;
    uint32_t bsw7  = brow & 7;

    // copy geometry (512 threads): row base = t>>3, chunk = t&7
    const int crr = t >> 3;      // 0..63
    const int ccc = t & 7;

    const int NCHUNK = D_MODEL / 64;   // 32

    // prologue: stages 0,1,2
#pragma unroll
    for (int pc = 0; pc < 3; pc++) {
        uint32_t abuf = sb + (uint32_t)pc * GSTAGE_BYTES;
        uint32_t bbuf = abuf + 16384u;
        const __half* Ag = Arow + (pc << 6);
        const __half* Bg = Brow + (pc << 6);
#pragma unroll
        for (int i = 0; i < 2; i++) {
            int r = crr + (i << 6);
            cp_async16(abuf + (r << 7) + ((uint32_t)(ccc ^ (r & 7)) << 4),
                       Ag + (size_t)r * D_MODEL + (ccc << 3));
        }
#pragma unroll
        for (int i = 0; i < 4; i++) {
            int r = crr + (i << 6);
            cp_async16(bbuf + (r << 7) + ((uint32_t)(ccc ^ (r & 7)) << 4),
                       Bg + (size_t)r * D_MODEL + (ccc << 3));
        }
        CP_COMMIT();
    }

    int stage = 0;
#pragma unroll 1
    for (int c = 0; c < NCHUNK; c++) {
        CP_WAIT(2);
        __syncthreads();

        uint32_t ab = sb + (uint32_t)stage * GSTAGE_BYTES;
        uint32_t bb = ab + 16384u;

#pragma unroll
        for (int s = 0; s < 4; s++) {
            uint32_t af[2][4], bf[4][4];
#pragma unroll
            for (int mt = 0; mt < 2; mt++) {
                uint32_t addr = ab + ((arow + mt * 16) << 7)
                                   + (((2u * s + acsel) ^ asw7) << 4);
                LDSM_X4(af[mt][0], af[mt][1], af[mt][2], af[mt][3], addr);
            }
#pragma unroll
            for (int p = 0; p < 4; p++) {
                uint32_t addr = bb + ((brow + p * 16) << 7)
                                   + (((2u * s + bcsel) ^ bsw7) << 4);
                LDSM_X4(bf[p][0], bf[p][1], bf[p][2], bf[p][3], addr);
            }
#pragma unroll
            for (int mt = 0; mt < 2; mt++)
#pragma unroll
                for (int nt = 0; nt < 8; nt++)
                    mma_f16(acc[mt][nt], af[mt],
                            bf[nt >> 1][(nt & 1) * 2],
                            bf[nt >> 1][(nt & 1) * 2 + 1]);
        }

        __syncthreads();

        if (c + 3 < NCHUNK) {
            int nc = c + 3;
            uint32_t abuf = sb + (uint32_t)((stage + 3) & 3) * GSTAGE_BYTES;
            uint32_t bbuf = abuf + 16384u;
            const __half* Ag = Arow + (nc << 6);
            const __half* Bg = Brow + (nc << 6);
#pragma unroll
            for (int i = 0; i < 2; i++) {
                int r = crr + (i << 6);
                cp_async16(abuf + (r << 7) + ((uint32_t)(ccc ^ (r & 7)) << 4),
                           Ag + (size_t)r * D_MODEL + (ccc << 3));
            }
#pragma unroll
            for (int i = 0; i < 4; i++) {
                int r = crr + (i << 6);
                cp_async16(bbuf + (r << 7) + ((uint32_t)(ccc ^ (r & 7)) << 4),
                           Bg + (size_t)r * D_MODEL + (ccc << 3));
            }
        }
        CP_COMMIT();

        stage = (stage + 1) & 3;
    }

    // ---- epilogue ----
    if (Cf != nullptr) {
#pragma unroll
        for (int mt = 0; mt < 2; mt++) {
            int re = row0 + wm + mt * 16 + (lane >> 2);
#pragma unroll
            for (int nt = 0; nt < 8; nt++) {
                int ce = col0 + wn + nt * 8 + ((lane & 3) << 1);
                *(float2*)(Cf + (size_t)re * D_MODEL + ce) =
                    make_float2(acc[mt][nt][0], acc[mt][nt][1]);
                *(float2*)(Cf + (size_t)(re + 8) * D_MODEL + ce) =
                    make_float2(acc[mt][nt][2], acc[mt][nt][3]);
            }
        }
    } else if (dovt) {
#pragma unroll
        for (int mt = 0; mt < 2; mt++) {
            int re = row0 + wm + mt * 16 + (lane >> 2);
#pragma unroll
            for (int nt = 0; nt < 8; nt++) {
                int ce = col0 + wn + nt * 8 + ((lane & 3) << 1);
                C[(size_t)ce * SEQ + re]           = __float2half_rn(acc[mt][nt][0]);
                C[(size_t)(ce + 1) * SEQ + re]     = __float2half_rn(acc[mt][nt][1]);
                C[(size_t)ce * SEQ + re + 8]       = __float2half_rn(acc[mt][nt][2]);
                C[(size_t)(ce + 1) * SEQ + re + 8] = __float2half_rn(acc[mt][nt][3]);
            }
        }
    } else {
#pragma unroll
        for (int mt = 0; mt < 2; mt++) {
            int re = row0 + wm + mt * 16 + (lane >> 2);
#pragma unroll
            for (int nt = 0; nt < 8; nt++) {
                int ce = col0 + wn + nt * 8 + ((lane & 3) << 1);
                float2 v0 = make_float2(acc[mt][nt][0], acc[mt][nt][1]);
                float2 v1 = make_float2(acc[mt][nt][2], acc[mt][nt][3]);
                if (dorope) {
                    int pidx = (ce & 127) >> 1;
                    float c0 = fc[(size_t)re * 64 + pidx];
                    float s0 = fs[(size_t)re * 64 + pidx];
                    float c1 = fc[(size_t)(re + 8) * 64 + pidx];
                    float s1 = fs[(size_t)(re + 8) * 64 + pidx];
                    v0 = make_float2(v0.x * c0 - v0.y * s0, v0.x * s0 + v0.y * c0);
                    v1 = make_float2(v1.x * c1 - v1.y * s1, v1.x * s1 + v1.y * c1);
                }
                *(uint32_t*)(C + (size_t)re * D_MODEL + ce)       = pack_half2(v0.x, v0.y);
                *(uint32_t*)(C + (size_t)(re + 8) * D_MODEL + ce) = pack_half2(v1.x, v1.y);
            }
        }
    }
}

// ---------------------------------------------------------------------------
// FlashAttention-2 fp16, 3-buffer K/Vt ring (unchanged from R9)
// ---------------------------------------------------------------------------
#define ATT_SMEM_BYTES (112 * 1024)

__global__ __launch_bounds__(256, 1) void attn_tc_kernel(
    const __half* __restrict__ Q, const __half* __restrict__ K,
    const __half* __restrict__ Vt, __half* __restrict__ O)
{
    extern __shared__ char smc[];
    uint32_t sb = smem_u32(smc);
    const uint32_t VBASE = sb + 49152u;
    const uint32_t PBASE = sb + 98304u;

    int t    = threadIdx.x;
    int lane = t & 31;
    int w    = t >> 5;
    int qt   = (int)gridDim.x - 1 - (int)blockIdx.x;
    int h    = blockIdx.y;
    int q0   = qt << 7;

    uint32_t arow  = (uint32_t)(lane & 15);
    uint32_t acsel = (uint32_t)((lane >> 4) & 1);
    uint32_t brow  = (uint32_t)((lane & 7) + ((lane >> 4) & 1) * 8);
    uint32_t bcsel = (uint32_t)((lane >> 3) & 1);
    uint32_t asw   = arow & 7;
    uint32_t bsw   = brow & 7;

    const __half* Kh  = K  + h * HEAD_DIM;
    const __half* Vth = Vt + (size_t)(h * HEAD_DIM) * SEQ;

    uint32_t qf[8][4];
    {
        const __half* Qg = Q + (size_t)q0 * D_MODEL + h * HEAD_DIM;
#pragma unroll
        for (int i = 0; i < 8; i++) {
            int lin = t + (i << 8);
            int r   = lin >> 4;
            int c   = lin & 15;
            cp_async16(sb + (r << 8) + ((uint32_t)(c ^ (r & 7)) << 4),
                       Qg + (size_t)r * D_MODEL + (c << 3));
        }
        CP_COMMIT();
        CP_WAIT(0);
        __syncthreads();
        uint32_t qrow = arow + (uint32_t)(w << 4);
        uint32_t qsw  = qrow & 7;
#pragma unroll
        for (int s = 0; s < 8; s++) {
            uint32_t addr = sb + (qrow << 8) + (((2u * s + acsel) ^ qsw) << 4);
            LDSM_X4(qf[s][0], qf[s][1], qf[s][2], qf[s][3], addr);
        }
        __syncthreads();
    }

    float oacc[16][4];
#pragma unroll
    for (int i = 0; i < 16; i++)
#pragma unroll
        for (int j = 0; j < 4; j++) oacc[i][j] = 0.0f;
    float mrow[2] = {-1e30f, -1e30f};
    float lrow[2] = {0.0f, 0.0f};

    const float scale = 0.08838834764831845f;
    const int   ktmax = 2 * qt + 1;
    const uint32_t pbase = PBASE + (uint32_t)(w << 11);

    auto issue_tile = [&](int kt) {
        uint32_t slot = (uint32_t)(kt % 3);
        const __half* Kg  = Kh  + ((size_t)kt << 6) * D_MODEL;
        const __half* Vtg = Vth + ((size_t)kt << 6);
#pragma unroll
        for (int i = 0; i < 4; i++) {
            int lin = t + (i << 8);
            int r   = lin >> 4;
            int c   = lin & 15;
            cp_async16(sb + slot * 16384u + (r << 8) + ((uint32_t)(c ^ (r & 7)) << 4),
                       Kg + (size_t)r * D_MODEL + (c << 3));
        }
#pragma unroll
        for (int i = 0; i < 4; i++) {
            int lin = t + (i << 8);
            int r   = lin >> 3;
            int c   = lin & 7;
            cp_async16(VBASE + slot * 16384u + (r << 7) + ((uint32_t)(c ^ (r & 7)) << 4),
                       Vtg + (size_t)r * SEQ + (c << 3));
        }
    };

    issue_tile(0); CP_COMMIT();
    issue_tile(1); CP_COMMIT();

#pragma unroll 1
    for (int kt = 0; kt <= ktmax; kt++) {
        if (kt + 2 <= ktmax) issue_tile(kt + 2);
        CP_COMMIT();
        CP_WAIT(2);
        __syncthreads();

        uint32_t slot = (uint32_t)(kt % 3);
        uint32_t kb = sb + slot * 16384u;
        uint32_t vb = VBASE + slot * 16384u;

        float sacc[8][4];
#pragma unroll
        for (int nt = 0; nt < 8; nt++)
#pragma unroll
            for (int e = 0; e < 4; e++) sacc[nt][e] = 0.0f;

#pragma unroll
        for (int s = 0; s < 8; s++) {
            uint32_t bf[4][4];
#pragma unroll
            for (int p = 0; p < 4; p++) {
                uint32_t addr = kb + ((brow + (uint32_t)(p << 4)) << 8)
                                   + (((2u * s + bcsel) ^ bsw) << 4);
                LDSM_X4(bf[p][0], bf[p][1], bf[p][2], bf[p][3], addr);
            }
#pragma unroll
            for (int nt = 0; nt < 8; nt++)
                mma_f16(sacc[nt], qf[s],
                        bf[nt >> 1][(nt & 1) * 2],
                        bf[nt >> 1][(nt & 1) * 2 + 1]);
        }

        bool need_mask = (kt >= 2 * qt);
        int grow = q0 + (w << 4) + (lane >> 2);
#pragma unroll
        for (int nt = 0; nt < 8; nt++) {
#pragma unroll
            for (int e = 0; e < 4; e++) {
                float v = sacc[nt][e] * scale;
                if (need_mask) {
                    int row = grow + (e >> 1) * 8;
                    int col = (kt << 6) + (nt << 3) + ((lane & 3) << 1) + (e & 1);
                    if (col > row) v = -1e30f;
                }
                sacc[nt][e] = v;
            }
        }

        float alpha[2];
#pragma unroll
        for (int half = 0; half < 2; half++) {
            float mx = -1e30f;
#pragma unroll
            for (int nt = 0; nt < 8; nt++)
                mx = fmaxf(mx, fmaxf(sacc[nt][2 * half], sacc[nt][2 * half + 1]));
            mx = fmaxf(mx, __shfl_xor_sync(0xffffffffu, mx, 1));
            mx = fmaxf(mx, __shfl_xor_sync(0xffffffffu, mx, 2));
            float mnew = fmaxf(mrow[half], mx);
            alpha[half] = __expf(mrow[half] - mnew);
            float sum = 0.0f;
#pragma unroll
            for (int nt = 0; nt < 8; nt++) {
                float p0 = __expf(sacc[nt][2 * half]     - mnew);
                float p1 = __expf(sacc[nt][2 * half + 1] - mnew);
                sacc[nt][2 * half]     = p0;
                sacc[nt][2 * half + 1] = p1;
                sum += p0 + p1;
            }
            sum += __shfl_xor_sync(0xffffffffu, sum, 1);
            sum += __shfl_xor_sync(0xffffffffu, sum, 2);
            lrow[half] = lrow[half] * alpha[half] + sum;
            mrow[half] = mnew;
        }
#pragma unroll
        for (int nt = 0; nt < 16; nt++) {
            oacc[nt][0] *= alpha[0];  oacc[nt][1] *= alpha[0];
            oacc[nt][2] *= alpha[1];  oacc[nt][3] *= alpha[1];
        }

        {
            uint32_t prow0 = (uint32_t)(lane >> 2);
            uint32_t prow1 = prow0 + 8;
            uint32_t psw   = prow0 & 7;
            uint32_t coff  = (uint32_t)((lane & 3) << 2);
#pragma unroll
            for (int nt = 0; nt < 8; nt++) {
                uint32_t chunk = ((uint32_t)nt ^ psw) << 4;
                asm volatile("st.shared.b32 [%0], %1;"
                             :: "r"(pbase + (prow0 << 7) + chunk + coff),
                                "r"(pack_half2(sacc[nt][0], sacc[nt][1])) : "memory");
                asm volatile("st.shared.b32 [%0], %1;"
                             :: "r"(pbase + (prow1 << 7) + chunk + coff),
                                "r"(pack_half2(sacc[nt][2], sacc[nt][3])) : "memory");
            }
        }
        __syncwarp();

#pragma unroll
        for (int s = 0; s < 4; s++) {
            uint32_t pf[4];
            uint32_t addrA = pbase + (arow << 7) + (((2u * s + acsel) ^ asw) << 4);
            LDSM_X4(pf[0], pf[1], pf[2], pf[3], addrA);
#pragma unroll
            for (int p = 0; p < 8; p++) {
                uint32_t bvf[4];
                uint32_t addrB = vb + ((brow + (uint32_t)(p << 4)) << 7)
                                    + (((2u * s + bcsel) ^ bsw) << 4);
                LDSM_X4(bvf[0], bvf[1], bvf[2], bvf[3], addrB);
                mma_f16(oacc[2 * p],     pf, bvf[0], bvf[1]);
                mma_f16(oacc[2 * p + 1], pf, bvf[2], bvf[3]);
            }
        }
        __syncthreads();
    }

    float inv0 = 1.0f / lrow[0];
    float inv1 = 1.0f / lrow[1];
    int row = q0 + (w << 4) + (lane >> 2);
#pragma unroll
    for (int nt = 0; nt < 16; nt++) {
        int col = h * HEAD_DIM + (nt << 3) + ((lane & 3) << 1);
        *(uint32_t*)(O + (size_t)row * D_MODEL + col) =
            pack_half2(oacc[nt][0] * inv0, oacc[nt][1] * inv0);
        *(uint32_t*)(O + (size_t)(row + 8) * D_MODEL + col) =
            pack_half2(oacc[nt][2] * inv1, oacc[nt][3] * inv1);
    }
}

// ---------------------------------------------------------------------------
extern "C" void kernel_launch(void* const* d_in, const int* in_sizes, int n_in,
                              void* d_out, int out_size)
{
    (void)in_sizes; (void)n_in; (void)out_size;
    const float* x  = (const float*)d_in[0];
    const float* fc = (const float*)d_in[1];
    const float* fs = (const float*)d_in[2];
    const float* wq = (const float*)d_in[4];
    const float* wk = (const float*)d_in[5];
    const float* wv = (const float*)d_in[6];
    const float* wo = (const float*)d_in[7];
    float* out = (float*)d_out;

    __half *Qp, *Kp, *Vtp, *Ap, *Xp, *WT4p;
    cudaGetSymbolAddress((void**)&Qp,   g_Q);
    cudaGetSymbolAddress((void**)&Kp,   g_K);
    cudaGetSymbolAddress((void**)&Vtp,  g_Vt);
    cudaGetSymbolAddress((void**)&Ap,   g_A);
    cudaGetSymbolAddress((void**)&Xp,   g_X);
    cudaGetSymbolAddress((void**)&WT4p, g_WT4);

    cudaFuncSetAttribute(gemm_tc_kernel, cudaFuncAttributeMaxDynamicSharedMemorySize,
                         GEMM_SMEM_BYTES);
    cudaFuncSetAttribute(attn_tc_kernel, cudaFuncAttributeMaxDynamicSharedMemorySize,
                         ATT_SMEM_BYTES);

    const size_t WSZ = (size_t)D_MODEL * D_MODEL;

    prep_kernel<<<dim3(64, 64, 5), dim3(32, 8)>>>(x, wq, wk, wv, wo, Xp, WT4p);

    gemm_tc_kernel<<<dim3(24, 16), 512, GEMM_SMEM_BYTES>>>(
        Xp, WT4p, Qp, Kp, Vtp, nullptr, fc, fs, 8, 2, 2);

    attn_tc_kernel<<<dim3(SEQ / 128, N_HEADS), 256, ATT_SMEM_BYTES>>>(Qp, Kp, Vtp, Ap);

    gemm_tc_kernel<<<dim3(8, 16), 512, GEMM_SMEM_BYTES>>>(
        Ap, WT4p + 3 * WSZ, nullptr, nullptr, nullptr, out, fc, fs, 8, 0, -1);
}